// round 2
// baseline (speedup 1.0000x reference)
#include <cuda_runtime.h>
#include <math.h>

// Problem constants
#define BB   32
#define LL   512
#define HH   1024
#define QQ   128
#define BQ   (BB * QQ)        // 4096 pair rows
#define K1   (3 * HH)          // 3072
#define N1   256               // VA_H
#define N2   128               // VA_H/2

// Scratch (static device globals — allowed; no runtime allocation)
__device__ float g_hpair[(size_t)BQ * K1];   // 50.3 MB
__device__ float g_x1[(size_t)BQ * N1];      // 4 MB
__device__ float g_x2[(size_t)BQ * N2];      // 2 MB

// ---------------------------------------------------------------------------
// Kernel 1: span pooling + pair-feature construction
// grid = 4096 blocks (one per (b,q) pair), 256 threads, each thread owns 4 dims
// Spans are int32 (JAX silently keeps int32 when x64 is disabled).
// All row indices clamped defensively to [0, LL-1].
// ---------------------------------------------------------------------------
__global__ void pool_pair_kernel(const float* __restrict__ hs,
                                 const int* __restrict__ spans)
{
    const int bq  = blockIdx.x;          // 0..4095
    const int b   = bq >> 7;             // /128
    const int tid = threadIdx.x;         // 0..255

    const int* sp = spans + (size_t)bq * 4;
    const int as = sp[0], ae = sp[1], os = sp[2], oe = sp[3];
    const bool av = (as >= 2) && (ae >= as);
    const bool ov = (os >= 2) && (oe >= os);

    const float* base = hs + (size_t)b * LL * HH;

    float aacc[4] = {0.f, 0.f, 0.f, 0.f};
    float oacc[4] = {0.f, 0.f, 0.f, 0.f};

    // aspect span (invalid -> sep row 1, count 1)
    {
        int s = av ? as : 1, e = av ? ae : 1;
        s = min(max(s, 0), LL - 1);
        e = min(max(e, 0), LL - 1);
        const int cnt = (e - s + 1) > 0 ? (e - s + 1) : 1;
        const float inv = 1.0f / (float)cnt;
        for (int r = s; r <= e; ++r) {
            const float* row = base + (size_t)r * HH;
            #pragma unroll
            for (int i = 0; i < 4; ++i) aacc[i] += row[tid + i * 256];
        }
        #pragma unroll
        for (int i = 0; i < 4; ++i) aacc[i] *= inv;
    }
    // opinion span
    {
        int s = ov ? os : 1, e = ov ? oe : 1;
        s = min(max(s, 0), LL - 1);
        e = min(max(e, 0), LL - 1);
        const int cnt = (e - s + 1) > 0 ? (e - s + 1) : 1;
        const float inv = 1.0f / (float)cnt;
        for (int r = s; r <= e; ++r) {
            const float* row = base + (size_t)r * HH;
            #pragma unroll
            for (int i = 0; i < 4; ++i) oacc[i] += row[tid + i * 256];
        }
        #pragma unroll
        for (int i = 0; i < 4; ++i) oacc[i] *= inv;
    }

    float* out = g_hpair + (size_t)bq * K1;
    #pragma unroll
    for (int i = 0; i < 4; ++i) {
        const int d = tid + i * 256;
        out[d]            = aacc[i];
        out[HH + d]       = oacc[i];
        out[2 * HH + d]   = aacc[i] * oacc[i];
    }
}

// ---------------------------------------------------------------------------
// Kernel 2/3: tiled fp32 GEMM  C[M,N] = gelu(A[M,K] @ W[N,K]^T + bias[N])
// BM=64, BN=64, BK=16, 256 threads, 4x4 per thread. M%64==0, N%64==0, K%16==0.
// ---------------------------------------------------------------------------
__device__ __forceinline__ float gelu_exact(float x)
{
    return 0.5f * x * (1.0f + erff(x * 0.70710678118654752f));
}

__global__ void gemm_gelu_kernel(const float* __restrict__ A,
                                 const float* __restrict__ W,
                                 const float* __restrict__ bias,
                                 float* __restrict__ C,
                                 int M, int N, int K)
{
    __shared__ float As[16][64];
    __shared__ float Bs[16][64];

    const int tx = threadIdx.x & 15;      // 0..15 -> N direction
    const int ty = threadIdx.x >> 4;      // 0..15 -> M direction
    const int m0 = blockIdx.y * 64;
    const int n0 = blockIdx.x * 64;

    // loader mapping: 256 threads load 64 rows x 16 cols as float4
    const int lr = threadIdx.x >> 2;            // 0..63 row within tile
    const int lk = (threadIdx.x & 3) * 4;       // 0,4,8,12

    float acc[4][4] = {};

    for (int k0 = 0; k0 < K; k0 += 16) {
        const float4 a4 = *(const float4*)(A + (size_t)(m0 + lr) * K + k0 + lk);
        const float4 b4 = *(const float4*)(W + (size_t)(n0 + lr) * K + k0 + lk);
        As[lk + 0][lr] = a4.x;  As[lk + 1][lr] = a4.y;
        As[lk + 2][lr] = a4.z;  As[lk + 3][lr] = a4.w;
        Bs[lk + 0][lr] = b4.x;  Bs[lk + 1][lr] = b4.y;
        Bs[lk + 2][lr] = b4.z;  Bs[lk + 3][lr] = b4.w;
        __syncthreads();

        #pragma unroll
        for (int k = 0; k < 16; ++k) {
            const float4 av = *(const float4*)&As[k][ty * 4];
            const float4 bv = *(const float4*)&Bs[k][tx * 4];
            const float ar[4] = {av.x, av.y, av.z, av.w};
            const float br[4] = {bv.x, bv.y, bv.z, bv.w};
            #pragma unroll
            for (int i = 0; i < 4; ++i)
                #pragma unroll
                for (int j = 0; j < 4; ++j)
                    acc[i][j] = fmaf(ar[i], br[j], acc[i][j]);
        }
        __syncthreads();
    }

    #pragma unroll
    for (int i = 0; i < 4; ++i) {
        const int r = m0 + ty * 4 + i;
        #pragma unroll
        for (int j = 0; j < 4; ++j) {
            const int c = n0 + tx * 4 + j;
            C[(size_t)r * N + c] = gelu_exact(acc[i][j] + bias[c]);
        }
    }
}

// ---------------------------------------------------------------------------
// Kernel 4: head  out[row, n] = sigmoid(x2[row] . W3[n] + b3[n]) * 8 + 1, masked
// 8192 threads total; each does a 128-length dot (float4-vectorized).
// ---------------------------------------------------------------------------
__global__ void head_kernel(const float* __restrict__ X,
                            const float* __restrict__ W3,
                            const float* __restrict__ b3,
                            const float* __restrict__ mask,
                            float* __restrict__ out)
{
    const int idx = blockIdx.x * blockDim.x + threadIdx.x;  // 0..8191
    if (idx >= BQ * 2) return;
    const int row = idx >> 1;
    const int n   = idx & 1;

    const float4* x = (const float4*)(X  + (size_t)row * N2);
    const float4* w = (const float4*)(W3 + (size_t)n   * N2);
    float s = 0.f;
    #pragma unroll
    for (int k = 0; k < N2 / 4; ++k) {
        const float4 xv = x[k];
        const float4 wv = w[k];
        s = fmaf(xv.x, wv.x, s);
        s = fmaf(xv.y, wv.y, s);
        s = fmaf(xv.z, wv.z, s);
        s = fmaf(xv.w, wv.w, s);
    }
    s += b3[n];
    const float sig = 1.0f / (1.0f + expf(-s));
    const float va  = sig * 8.0f + 1.0f;
    const float mk  = (mask[row] >= 0.5f) ? 1.0f : 0.0f;
    out[idx] = va * mk;
}

// ---------------------------------------------------------------------------
// Launch
// ---------------------------------------------------------------------------
extern "C" void kernel_launch(void* const* d_in, const int* in_sizes, int n_in,
                              void* d_out, int out_size)
{
    const float* hidden = (const float*)d_in[0];
    const int*   spans  = (const int*)d_in[1];
    const float* mask   = (const float*)d_in[2];
    const float* W1     = (const float*)d_in[3];
    const float* b1     = (const float*)d_in[4];
    const float* W2     = (const float*)d_in[5];
    const float* b2     = (const float*)d_in[6];
    const float* W3     = (const float*)d_in[7];
    const float* b3     = (const float*)d_in[8];
    float*       out    = (float*)d_out;

    float* hpair; cudaGetSymbolAddress((void**)&hpair, g_hpair);
    float* x1;    cudaGetSymbolAddress((void**)&x1,    g_x1);
    float* x2;    cudaGetSymbolAddress((void**)&x2,    g_x2);

    // 1) pooling + pair features
    pool_pair_kernel<<<BQ, 256>>>(hidden, spans);

    // 2) layer 1: (4096 x 3072) @ (3072 x 256)^T  + gelu
    {
        dim3 grid(N1 / 64, BQ / 64);
        gemm_gelu_kernel<<<grid, 256>>>(hpair, W1, b1, x1, BQ, N1, K1);
    }
    // 3) layer 2: (4096 x 256) @ (256 x 128)^T + gelu
    {
        dim3 grid(N2 / 64, BQ / 64);
        gemm_gelu_kernel<<<grid, 256>>>(x1, W2, b2, x2, BQ, N2, N1);
    }
    // 4) head
    head_kernel<<<(BQ * 2 + 255) / 256, 256>>>(x2, W3, b3, mask, out);
}

// round 3
// speedup vs baseline: 1.6897x; 1.6897x over previous
#include <cuda_runtime.h>
#include <cuda_fp16.h>
#include <math.h>
#include <stdint.h>

// Problem constants
#define BB   32
#define LL   512
#define HH   1024
#define QQ   128
#define BQ   (BB * QQ)        // 4096 pair rows
#define K1   (3 * HH)          // 3072
#define N1   256               // VA_H
#define N2   128               // VA_H/2

// Scratch (static device globals)
__device__ __half g_Ah[(size_t)BQ * K1];     // h_pair hi, 25 MB
__device__ __half g_Al[(size_t)BQ * K1];     // h_pair lo, 25 MB
__device__ __half g_W1h[(size_t)N1 * K1];    // 1.5 MB
__device__ __half g_W1l[(size_t)N1 * K1];    // 1.5 MB
__device__ float  g_x1[(size_t)BQ * N1];     // 4 MB
__device__ float  g_x2[(size_t)BQ * N2];     // 2 MB

// ---------------------------------------------------------------------------
// Split W1 into fp16 hi/lo
// ---------------------------------------------------------------------------
__global__ void split_w1_kernel(const float* __restrict__ W1)
{
    const int i = blockIdx.x * blockDim.x + threadIdx.x;
    if (i >= N1 * K1) return;
    const float v  = W1[i];
    const __half h = __float2half_rn(v);
    g_W1h[i] = h;
    g_W1l[i] = __float2half_rn(v - __half2float(h));
}

// ---------------------------------------------------------------------------
// Kernel 1: span pooling + pair features, emitted as fp16 hi/lo
// grid = 4096 blocks, 256 threads, 4 dims per thread
// ---------------------------------------------------------------------------
__device__ __forceinline__ void store_split(__half* hi, __half* lo, size_t idx, float v)
{
    const __half h = __float2half_rn(v);
    hi[idx] = h;
    lo[idx] = __float2half_rn(v - __half2float(h));
}

__global__ void pool_pair_kernel(const float* __restrict__ hs,
                                 const int* __restrict__ spans)
{
    const int bq  = blockIdx.x;
    const int b   = bq >> 7;
    const int tid = threadIdx.x;

    const int* sp = spans + (size_t)bq * 4;
    const int as = sp[0], ae = sp[1], os = sp[2], oe = sp[3];
    const bool av = (as >= 2) && (ae >= as);
    const bool ov = (os >= 2) && (oe >= os);

    const float* base = hs + (size_t)b * LL * HH;

    float aacc[4] = {0.f, 0.f, 0.f, 0.f};
    float oacc[4] = {0.f, 0.f, 0.f, 0.f};

    {
        int s = av ? as : 1, e = av ? ae : 1;
        s = min(max(s, 0), LL - 1);
        e = min(max(e, 0), LL - 1);
        const float inv = 1.0f / (float)((e - s + 1) > 0 ? (e - s + 1) : 1);
        for (int r = s; r <= e; ++r) {
            const float* row = base + (size_t)r * HH;
            #pragma unroll
            for (int i = 0; i < 4; ++i) aacc[i] += row[tid + i * 256];
        }
        #pragma unroll
        for (int i = 0; i < 4; ++i) aacc[i] *= inv;
    }
    {
        int s = ov ? os : 1, e = ov ? oe : 1;
        s = min(max(s, 0), LL - 1);
        e = min(max(e, 0), LL - 1);
        const float inv = 1.0f / (float)((e - s + 1) > 0 ? (e - s + 1) : 1);
        for (int r = s; r <= e; ++r) {
            const float* row = base + (size_t)r * HH;
            #pragma unroll
            for (int i = 0; i < 4; ++i) oacc[i] += row[tid + i * 256];
        }
        #pragma unroll
        for (int i = 0; i < 4; ++i) oacc[i] *= inv;
    }

    const size_t rowoff = (size_t)bq * K1;
    #pragma unroll
    for (int i = 0; i < 4; ++i) {
        const int d = tid + i * 256;
        store_split(g_Ah, g_Al, rowoff + d,            aacc[i]);
        store_split(g_Ah, g_Al, rowoff + HH + d,       oacc[i]);
        store_split(g_Ah, g_Al, rowoff + 2 * HH + d,   aacc[i] * oacc[i]);
    }
}

// ---------------------------------------------------------------------------
// GELU (exact erf)
// ---------------------------------------------------------------------------
__device__ __forceinline__ float gelu_exact(float x)
{
    return 0.5f * x * (1.0f + erff(x * 0.70710678118654752f));
}

// ---------------------------------------------------------------------------
// GEMM1: x1 = gelu(A @ W1^T + b1), A = hi/lo fp16 split, tensor cores.
// BM=64, BN=128, BK=32. 8 warps = 2(M) x 4(N), each warp 32x32.
// grid = (N1/128, BQ/64) = (2, 64) = 128 blocks.
// ---------------------------------------------------------------------------
#define PADW 20          // words per smem row: 16 data (32 fp16) + 4 pad

__device__ __forceinline__ void mma16816(float c[4],
                                         const uint32_t a[4],
                                         const uint32_t b[2])
{
    asm volatile(
        "mma.sync.aligned.m16n8k16.row.col.f32.f16.f16.f32 "
        "{%0,%1,%2,%3}, {%4,%5,%6,%7}, {%8,%9}, {%0,%1,%2,%3};\n"
        : "+f"(c[0]), "+f"(c[1]), "+f"(c[2]), "+f"(c[3])
        : "r"(a[0]), "r"(a[1]), "r"(a[2]), "r"(a[3]),
          "r"(b[0]), "r"(b[1]));
}

__global__ __launch_bounds__(256, 1)
void gemm1_mma_kernel(const float* __restrict__ bias,
                      float* __restrict__ C)
{
    __shared__ uint32_t As_h[64 * PADW];
    __shared__ uint32_t As_l[64 * PADW];
    __shared__ uint32_t Bs_h[128 * PADW];
    __shared__ uint32_t Bs_l[128 * PADW];

    const int tid   = threadIdx.x;
    const int warp  = tid >> 5;
    const int lane  = tid & 31;
    const int warpM = warp >> 2;          // 0..1
    const int warpN = warp & 3;           // 0..3
    const int lane4 = lane >> 2;          // 0..7
    const int lanem = lane & 3;           // 0..3

    const int m0 = blockIdx.y * 64;
    const int n0 = blockIdx.x * 128;

    // loader mapping
    const int lrA  = tid >> 2;            // 0..63
    const int segA = tid & 3;             // 0..3 (16B chunks)
    const int lrB0 = tid >> 2;            // rows 0..63 and +64
    const int segB = tid & 3;

    float acc[2][4][4];
    #pragma unroll
    for (int i = 0; i < 2; ++i)
        #pragma unroll
        for (int j = 0; j < 4; ++j)
            #pragma unroll
            for (int k = 0; k < 4; ++k) acc[i][j][k] = 0.f;

    for (int k0 = 0; k0 < K1; k0 += 32) {
        // ---- load tiles to smem ----
        {
            const uint4 a_h = *(const uint4*)(g_Ah + (size_t)(m0 + lrA) * K1 + k0 + segA * 8);
            const uint4 a_l = *(const uint4*)(g_Al + (size_t)(m0 + lrA) * K1 + k0 + segA * 8);
            *(uint4*)&As_h[lrA * PADW + segA * 4] = a_h;
            *(uint4*)&As_l[lrA * PADW + segA * 4] = a_l;

            const uint4 b_h0 = *(const uint4*)(g_W1h + (size_t)(n0 + lrB0) * K1 + k0 + segB * 8);
            const uint4 b_l0 = *(const uint4*)(g_W1l + (size_t)(n0 + lrB0) * K1 + k0 + segB * 8);
            *(uint4*)&Bs_h[lrB0 * PADW + segB * 4] = b_h0;
            *(uint4*)&Bs_l[lrB0 * PADW + segB * 4] = b_l0;
            const uint4 b_h1 = *(const uint4*)(g_W1h + (size_t)(n0 + lrB0 + 64) * K1 + k0 + segB * 8);
            const uint4 b_l1 = *(const uint4*)(g_W1l + (size_t)(n0 + lrB0 + 64) * K1 + k0 + segB * 8);
            *(uint4*)&Bs_h[(lrB0 + 64) * PADW + segB * 4] = b_h1;
            *(uint4*)&Bs_l[(lrB0 + 64) * PADW + segB * 4] = b_l1;
        }
        __syncthreads();

        #pragma unroll
        for (int sub = 0; sub < 2; ++sub) {
            const int kw = sub * 8 + lanem;

            uint32_t ah[2][4], al[2][4];
            #pragma unroll
            for (int mt = 0; mt < 2; ++mt) {
                const int r = warpM * 32 + mt * 16 + lane4;
                ah[mt][0] = As_h[r * PADW + kw];
                ah[mt][1] = As_h[(r + 8) * PADW + kw];
                ah[mt][2] = As_h[r * PADW + kw + 4];
                ah[mt][3] = As_h[(r + 8) * PADW + kw + 4];
                al[mt][0] = As_l[r * PADW + kw];
                al[mt][1] = As_l[(r + 8) * PADW + kw];
                al[mt][2] = As_l[r * PADW + kw + 4];
                al[mt][3] = As_l[(r + 8) * PADW + kw + 4];
            }

            #pragma unroll
            for (int nt = 0; nt < 4; ++nt) {
                const int n = warpN * 32 + nt * 8 + lane4;
                uint32_t bh[2], bl[2];
                bh[0] = Bs_h[n * PADW + kw];
                bh[1] = Bs_h[n * PADW + kw + 4];
                bl[0] = Bs_l[n * PADW + kw];
                bl[1] = Bs_l[n * PADW + kw + 4];

                #pragma unroll
                for (int mt = 0; mt < 2; ++mt) {
                    mma16816(acc[mt][nt], ah[mt], bh);
                    mma16816(acc[mt][nt], ah[mt], bl);
                    mma16816(acc[mt][nt], al[mt], bh);
                }
            }
        }
        __syncthreads();
    }

    // ---- epilogue: bias + gelu ----
    #pragma unroll
    for (int mt = 0; mt < 2; ++mt) {
        #pragma unroll
        for (int nt = 0; nt < 4; ++nt) {
            const int c0 = n0 + warpN * 32 + nt * 8 + lanem * 2;
            const float bv0 = bias[c0];
            const float bv1 = bias[c0 + 1];
            const int r0 = m0 + warpM * 32 + mt * 16 + lane4;

            float2 v0, v1;
            v0.x = gelu_exact(acc[mt][nt][0] + bv0);
            v0.y = gelu_exact(acc[mt][nt][1] + bv1);
            v1.x = gelu_exact(acc[mt][nt][2] + bv0);
            v1.y = gelu_exact(acc[mt][nt][3] + bv1);
            *(float2*)(C + (size_t)r0 * N1 + c0)       = v0;
            *(float2*)(C + (size_t)(r0 + 8) * N1 + c0) = v1;
        }
    }
}

// ---------------------------------------------------------------------------
// GEMM2 (fp32 SIMT, small): C = gelu(A[M,K] @ W[N,K]^T + b)
// BM=64, BN=64, BK=16, 256 threads, 4x4/thread
// ---------------------------------------------------------------------------
__global__ void gemm_gelu_kernel(const float* __restrict__ A,
                                 const float* __restrict__ W,
                                 const float* __restrict__ bias,
                                 float* __restrict__ C,
                                 int M, int N, int K)
{
    __shared__ float As[16][64];
    __shared__ float Bs[16][64];

    const int tx = threadIdx.x & 15;
    const int ty = threadIdx.x >> 4;
    const int m0 = blockIdx.y * 64;
    const int n0 = blockIdx.x * 64;

    const int lr = threadIdx.x >> 2;
    const int lk = (threadIdx.x & 3) * 4;

    float acc[4][4] = {};

    for (int k0 = 0; k0 < K; k0 += 16) {
        const float4 a4 = *(const float4*)(A + (size_t)(m0 + lr) * K + k0 + lk);
        const float4 b4 = *(const float4*)(W + (size_t)(n0 + lr) * K + k0 + lk);
        As[lk + 0][lr] = a4.x;  As[lk + 1][lr] = a4.y;
        As[lk + 2][lr] = a4.z;  As[lk + 3][lr] = a4.w;
        Bs[lk + 0][lr] = b4.x;  Bs[lk + 1][lr] = b4.y;
        Bs[lk + 2][lr] = b4.z;  Bs[lk + 3][lr] = b4.w;
        __syncthreads();

        #pragma unroll
        for (int k = 0; k < 16; ++k) {
            const float4 av = *(const float4*)&As[k][ty * 4];
            const float4 bv = *(const float4*)&Bs[k][tx * 4];
            const float ar[4] = {av.x, av.y, av.z, av.w};
            const float br[4] = {bv.x, bv.y, bv.z, bv.w};
            #pragma unroll
            for (int i = 0; i < 4; ++i)
                #pragma unroll
                for (int j = 0; j < 4; ++j)
                    acc[i][j] = fmaf(ar[i], br[j], acc[i][j]);
        }
        __syncthreads();
    }

    #pragma unroll
    for (int i = 0; i < 4; ++i) {
        const int r = m0 + ty * 4 + i;
        #pragma unroll
        for (int j = 0; j < 4; ++j) {
            const int c = n0 + tx * 4 + j;
            C[(size_t)r * N + c] = gelu_exact(acc[i][j] + bias[c]);
        }
    }
}

// ---------------------------------------------------------------------------
// Head: one warp per row, shuffle reduction over K=128.
// grid = 64 blocks x 256 threads = 512 warps, 8 rows per warp.
// ---------------------------------------------------------------------------
__global__ void head_kernel(const float* __restrict__ X,
                            const float* __restrict__ W3,
                            const float* __restrict__ b3,
                            const float* __restrict__ mask,
                            float* __restrict__ out)
{
    const int gwarp = (blockIdx.x * blockDim.x + threadIdx.x) >> 5;
    const int lane  = threadIdx.x & 31;

    const float4 w0 = ((const float4*)W3)[lane];        // row 0
    const float4 w1 = ((const float4*)W3)[32 + lane];   // row 1
    const float b30 = b3[0], b31 = b3[1];

    const int rowbase = gwarp * 8;
    #pragma unroll
    for (int i = 0; i < 8; ++i) {
        const int row = rowbase + i;
        const float4 xv = ((const float4*)(X + (size_t)row * N2))[lane];
        float s0 = xv.x * w0.x + xv.y * w0.y + xv.z * w0.z + xv.w * w0.w;
        float s1 = xv.x * w1.x + xv.y * w1.y + xv.z * w1.z + xv.w * w1.w;
        #pragma unroll
        for (int off = 16; off > 0; off >>= 1) {
            s0 += __shfl_xor_sync(0xFFFFFFFFu, s0, off);
            s1 += __shfl_xor_sync(0xFFFFFFFFu, s1, off);
        }
        if (lane == 0) {
            const float mk = (mask[row] >= 0.5f) ? 1.0f : 0.0f;
            const float v0 = (1.0f / (1.0f + expf(-(s0 + b30)))) * 8.0f + 1.0f;
            const float v1 = (1.0f / (1.0f + expf(-(s1 + b31)))) * 8.0f + 1.0f;
            out[row * 2 + 0] = v0 * mk;
            out[row * 2 + 1] = v1 * mk;
        }
    }
}

// ---------------------------------------------------------------------------
// Launch
// ---------------------------------------------------------------------------
extern "C" void kernel_launch(void* const* d_in, const int* in_sizes, int n_in,
                              void* d_out, int out_size)
{
    const float* hidden = (const float*)d_in[0];
    const int*   spans  = (const int*)d_in[1];
    const float* mask   = (const float*)d_in[2];
    const float* W1     = (const float*)d_in[3];
    const float* b1     = (const float*)d_in[4];
    const float* W2     = (const float*)d_in[5];
    const float* b2     = (const float*)d_in[6];
    const float* W3     = (const float*)d_in[7];
    const float* b3     = (const float*)d_in[8];
    float*       out    = (float*)d_out;

    float* x1; cudaGetSymbolAddress((void**)&x1, g_x1);
    float* x2; cudaGetSymbolAddress((void**)&x2, g_x2);

    // 0) split W1 to fp16 hi/lo
    split_w1_kernel<<<(N1 * K1 + 1023) / 1024, 1024>>>(W1);

    // 1) pooling + pair features (fp16 hi/lo)
    pool_pair_kernel<<<BQ, 256>>>(hidden, spans);

    // 2) layer 1 via tensor cores
    {
        dim3 grid(N1 / 128, BQ / 64);
        gemm1_mma_kernel<<<grid, 256>>>(b1, x1);
    }

    // 3) layer 2: (4096 x 256) @ (256 x 128)^T + gelu  (fp32)
    {
        dim3 grid(N2 / 64, BQ / 64);
        gemm_gelu_kernel<<<grid, 256>>>(x1, W2, b2, x2, BQ, N2, N1);
    }

    // 4) head
    head_kernel<<<64, 256>>>(x2, W3, b3, mask, out);
}

// round 5
// speedup vs baseline: 2.2111x; 1.3086x over previous
#include <cuda_runtime.h>
#include <cuda_fp16.h>
#include <math.h>
#include <stdint.h>

// Problem constants
#define BB   32
#define LL   512
#define HH   1024
#define QQ   128
#define BQ   (BB * QQ)        // 4096 pair rows
#define K1   (3 * HH)          // 3072
#define N1   256               // VA_H
#define N2   128               // VA_H/2

// Scratch (static device globals)
__device__ __half g_Ah[(size_t)BQ * K1];
__device__ __half g_Al[(size_t)BQ * K1];
__device__ __half g_W1h[(size_t)N1 * K1];
__device__ __half g_W1l[(size_t)N1 * K1];
__device__ __half g_W2h[(size_t)N2 * N1];
__device__ __half g_W2l[(size_t)N2 * N1];
__device__ __half g_x1h[(size_t)BQ * N1];
__device__ __half g_x1l[(size_t)BQ * N1];
__device__ float  g_x2[(size_t)BQ * N2];

// ---------------------------------------------------------------------------
// helpers
// ---------------------------------------------------------------------------
__device__ __forceinline__ uint32_t smem_u32(const void* p) {
    uint32_t a;
    asm("{ .reg .u64 t; cvta.to.shared.u64 t, %1; cvt.u32.u64 %0, t; }"
        : "=r"(a) : "l"(p));
    return a;
}

#define CP_ASYNC16(dst, src) \
    asm volatile("cp.async.cg.shared.global [%0], [%1], 16;" :: "r"(dst), "l"(src) : "memory")
#define CP_COMMIT() asm volatile("cp.async.commit_group;" ::: "memory")
#define CP_WAIT0()  asm volatile("cp.async.wait_group 0;" ::: "memory")
#define CP_WAIT1()  asm volatile("cp.async.wait_group 1;" ::: "memory")

__device__ __forceinline__ void mma16816(float c[4],
                                         const uint32_t a[4],
                                         const uint32_t b[2])
{
    asm volatile(
        "mma.sync.aligned.m16n8k16.row.col.f32.f16.f16.f32 "
        "{%0,%1,%2,%3}, {%4,%5,%6,%7}, {%8,%9}, {%0,%1,%2,%3};\n"
        : "+f"(c[0]), "+f"(c[1]), "+f"(c[2]), "+f"(c[3])
        : "r"(a[0]), "r"(a[1]), "r"(a[2]), "r"(a[3]),
          "r"(b[0]), "r"(b[1]));
}

__device__ __forceinline__ float gelu_exact(float x) {
    return 0.5f * x * (1.0f + erff(x * 0.70710678118654752f));
}

// ---------------------------------------------------------------------------
// Weight prep: split W1 and W2 into fp16 hi/lo
// ---------------------------------------------------------------------------
__global__ void prep_w_kernel(const float* __restrict__ W1,
                              const float* __restrict__ W2)
{
    const int i = blockIdx.x * blockDim.x + threadIdx.x;
    if (i < N1 * K1) {
        const float v  = W1[i];
        const __half h = __float2half_rn(v);
        g_W1h[i] = h;
        g_W1l[i] = __float2half_rn(v - __half2float(h));
    }
    if (i < N2 * N1) {
        const float v  = W2[i];
        const __half h = __float2half_rn(v);
        g_W2h[i] = h;
        g_W2l[i] = __float2half_rn(v - __half2float(h));
    }
}

// ---------------------------------------------------------------------------
// Span pooling + pair features (fp16 hi/lo), float4 loads, half4 stores.
// grid = 4096 blocks, 256 threads; thread t owns dims [4t, 4t+4)
// ---------------------------------------------------------------------------
__device__ __forceinline__ void split_store4(__half* hi, __half* lo,
                                             size_t idx, float4 v)
{
    const __half h0 = __float2half_rn(v.x);
    const __half h1 = __float2half_rn(v.y);
    const __half h2 = __float2half_rn(v.z);
    const __half h3 = __float2half_rn(v.w);
    __half2 hh[2] = { __halves2half2(h0, h1), __halves2half2(h2, h3) };
    __half2 ll[2] = {
        __halves2half2(__float2half_rn(v.x - __half2float(h0)),
                       __float2half_rn(v.y - __half2float(h1))),
        __halves2half2(__float2half_rn(v.z - __half2float(h2)),
                       __float2half_rn(v.w - __half2float(h3))) };
    *(uint2*)(hi + idx) = *(uint2*)hh;
    *(uint2*)(lo + idx) = *(uint2*)ll;
}

__global__ void pool_pair_kernel(const float* __restrict__ hs,
                                 const int* __restrict__ spans)
{
    const int bq  = blockIdx.x;
    const int b   = bq >> 7;
    const int tid = threadIdx.x;

    const int* sp = spans + (size_t)bq * 4;
    const int as = sp[0], ae = sp[1], os = sp[2], oe = sp[3];
    const bool av = (as >= 2) && (ae >= as);
    const bool ov = (os >= 2) && (oe >= os);

    const float* base = hs + (size_t)b * LL * HH + 4 * tid;

    float4 aacc = {0.f, 0.f, 0.f, 0.f};
    float4 oacc = {0.f, 0.f, 0.f, 0.f};

    {
        int s = av ? as : 1, e = av ? ae : 1;
        s = min(max(s, 0), LL - 1);
        e = min(max(e, 0), LL - 1);
        const float inv = 1.0f / (float)((e - s + 1) > 0 ? (e - s + 1) : 1);
        for (int r = s; r <= e; ++r) {
            const float4 v = *(const float4*)(base + (size_t)r * HH);
            aacc.x += v.x; aacc.y += v.y; aacc.z += v.z; aacc.w += v.w;
        }
        aacc.x *= inv; aacc.y *= inv; aacc.z *= inv; aacc.w *= inv;
    }
    {
        int s = ov ? os : 1, e = ov ? oe : 1;
        s = min(max(s, 0), LL - 1);
        e = min(max(e, 0), LL - 1);
        const float inv = 1.0f / (float)((e - s + 1) > 0 ? (e - s + 1) : 1);
        for (int r = s; r <= e; ++r) {
            const float4 v = *(const float4*)(base + (size_t)r * HH);
            oacc.x += v.x; oacc.y += v.y; oacc.z += v.z; oacc.w += v.w;
        }
        oacc.x *= inv; oacc.y *= inv; oacc.z *= inv; oacc.w *= inv;
    }

    float4 pacc;
    pacc.x = aacc.x * oacc.x;  pacc.y = aacc.y * oacc.y;
    pacc.z = aacc.z * oacc.z;  pacc.w = aacc.w * oacc.w;

    const size_t rowoff = (size_t)bq * K1 + 4 * tid;
    split_store4(g_Ah, g_Al, rowoff,           aacc);
    split_store4(g_Ah, g_Al, rowoff + HH,      oacc);
    split_store4(g_Ah, g_Al, rowoff + 2 * HH,  pacc);
}

// ---------------------------------------------------------------------------
// Pipelined mma.sync GEMM with fp16 hi/lo split (3 passes, fp32 accum):
//   C[M,N] = epilogue(A[M,K] @ B[N,K]^T + bias)
// BM=64, BN=128, BK=32, 256 threads = 8 warps (2M x 4N), warp tile 32x32.
// 2-stage cp.async double buffering.
// mode 0: C fp32 = gelu(acc+bias)   (out_f)
// mode 1: gelu(acc+bias) split to fp16 hi/lo (out_h, out_l)
// ---------------------------------------------------------------------------
#define PADW 20                     // words per 32-half row (16 data + 4 pad)
#define AW   (64 * PADW)            // 1280 words per A buffer
#define BW   (128 * PADW)           // 2560 words per B buffer
#define STW  (2 * AW + 2 * BW)      // 7680 words per stage (30720 B)
#define GEMM_SMEM_BYTES (2 * STW * 4)   // 61440 B

__global__ __launch_bounds__(256)
void mma_gemm_kernel(const __half* __restrict__ Ah, const __half* __restrict__ Al,
                     const __half* __restrict__ Bh, const __half* __restrict__ Bl,
                     int lda, int ldb, int K,
                     const float* __restrict__ bias,
                     float* __restrict__ out_f,
                     __half* __restrict__ out_h, __half* __restrict__ out_l,
                     int out_ld, int mode)
{
    extern __shared__ uint32_t sm[];
    const uint32_t smem32 = smem_u32(sm);

    const int tid   = threadIdx.x;
    const int warp  = tid >> 5;
    const int lane  = tid & 31;
    const int warpM = warp >> 2;
    const int warpN = warp & 3;
    const int lane4 = lane >> 2;
    const int lanem = lane & 3;

    const int m0 = blockIdx.y * 64;
    const int n0 = blockIdx.x * 128;
    const int nk = K >> 5;

    // ---- async loader: 1536 16B chunks / 256 threads = 6 per thread ----
    auto load_stage = [&](int c) {
        const uint32_t sb = smem32 + (uint32_t)(c & 1) * (STW * 4);
        const int kk = c * 32;
        #pragma unroll
        for (int i = 0; i < 6; ++i) {
            const int u = i * 256 + tid;
            const __half* src;
            uint32_t dstw;
            if (u < 512) {
                const int hsel = u >> 8;
                const int v = u & 255;
                const int row = v >> 2, seg = v & 3;
                src  = (hsel ? Al : Ah) + (size_t)(m0 + row) * lda + kk + seg * 8;
                dstw = (hsel ? AW : 0) + row * PADW + seg * 4;
            } else {
                const int v = u - 512;
                const int hsel = v >> 9;
                const int w = v & 511;
                const int row = w >> 2, seg = w & 3;
                src  = (hsel ? Bl : Bh) + (size_t)(n0 + row) * ldb + kk + seg * 8;
                dstw = 2 * AW + (hsel ? BW : 0) + row * PADW + seg * 4;
            }
            CP_ASYNC16(sb + dstw * 4, src);
        }
        CP_COMMIT();
    };

    float acc[2][4][4];
    #pragma unroll
    for (int i = 0; i < 2; ++i)
        #pragma unroll
        for (int j = 0; j < 4; ++j)
            #pragma unroll
            for (int k = 0; k < 4; ++k) acc[i][j][k] = 0.f;

    load_stage(0);

    for (int c = 0; c < nk; ++c) {
        if (c + 1 < nk) { load_stage(c + 1); CP_WAIT1(); }
        else            { CP_WAIT0(); }
        __syncthreads();

        const uint32_t* As_h = sm + (c & 1) * STW;
        const uint32_t* As_l = As_h + AW;
        const uint32_t* Bs_h = As_h + 2 * AW;
        const uint32_t* Bs_l = Bs_h + BW;

        #pragma unroll
        for (int sub = 0; sub < 2; ++sub) {
            const int kw = sub * 8 + lanem;

            uint32_t ah[2][4], al[2][4];
            #pragma unroll
            for (int mt = 0; mt < 2; ++mt) {
                const int r = warpM * 32 + mt * 16 + lane4;
                ah[mt][0] = As_h[r * PADW + kw];
                ah[mt][1] = As_h[(r + 8) * PADW + kw];
                ah[mt][2] = As_h[r * PADW + kw + 4];
                ah[mt][3] = As_h[(r + 8) * PADW + kw + 4];
                al[mt][0] = As_l[r * PADW + kw];
                al[mt][1] = As_l[(r + 8) * PADW + kw];
                al[mt][2] = As_l[r * PADW + kw + 4];
                al[mt][3] = As_l[(r + 8) * PADW + kw + 4];
            }

            #pragma unroll
            for (int nt = 0; nt < 4; ++nt) {
                const int n = warpN * 32 + nt * 8 + lane4;
                uint32_t bh[2], bl[2];
                bh[0] = Bs_h[n * PADW + kw];
                bh[1] = Bs_h[n * PADW + kw + 4];
                bl[0] = Bs_l[n * PADW + kw];
                bl[1] = Bs_l[n * PADW + kw + 4];

                #pragma unroll
                for (int mt = 0; mt < 2; ++mt) {
                    mma16816(acc[mt][nt], ah[mt], bh);
                    mma16816(acc[mt][nt], ah[mt], bl);
                    mma16816(acc[mt][nt], al[mt], bh);
                }
            }
        }
        __syncthreads();
    }

    // ---- epilogue: bias + gelu (+ optional fp16 split) ----
    #pragma unroll
    for (int mt = 0; mt < 2; ++mt) {
        #pragma unroll
        for (int nt = 0; nt < 4; ++nt) {
            const int c0 = n0 + warpN * 32 + nt * 8 + lanem * 2;
            const float bv0 = bias[c0];
            const float bv1 = bias[c0 + 1];
            const int r0 = m0 + warpM * 32 + mt * 16 + lane4;

            const float g00 = gelu_exact(acc[mt][nt][0] + bv0);
            const float g01 = gelu_exact(acc[mt][nt][1] + bv1);
            const float g10 = gelu_exact(acc[mt][nt][2] + bv0);
            const float g11 = gelu_exact(acc[mt][nt][3] + bv1);

            if (mode == 0) {
                *(float2*)(out_f + (size_t)r0 * out_ld + c0)       = make_float2(g00, g01);
                *(float2*)(out_f + (size_t)(r0 + 8) * out_ld + c0) = make_float2(g10, g11);
            } else {
                const __half h00 = __float2half_rn(g00), h01 = __float2half_rn(g01);
                const __half h10 = __float2half_rn(g10), h11 = __float2half_rn(g11);
                __half2 v0h = __halves2half2(h00, h01);
                __half2 v1h = __halves2half2(h10, h11);
                __half2 v0l = __halves2half2(__float2half_rn(g00 - __half2float(h00)),
                                             __float2half_rn(g01 - __half2float(h01)));
                __half2 v1l = __halves2half2(__float2half_rn(g10 - __half2float(h10)),
                                             __float2half_rn(g11 - __half2float(h11)));
                *(__half2*)(out_h + (size_t)r0 * out_ld + c0)       = v0h;
                *(__half2*)(out_h + (size_t)(r0 + 8) * out_ld + c0) = v1h;
                *(__half2*)(out_l + (size_t)r0 * out_ld + c0)       = v0l;
                *(__half2*)(out_l + (size_t)(r0 + 8) * out_ld + c0) = v1l;
            }
        }
    }
}

// ---------------------------------------------------------------------------
// Head: one warp per 8 rows, shuffle reduction over K=128
// ---------------------------------------------------------------------------
__global__ void head_kernel(const float* __restrict__ X,
                            const float* __restrict__ W3,
                            const float* __restrict__ b3,
                            const float* __restrict__ mask,
                            float* __restrict__ out)
{
    const int gwarp = (blockIdx.x * blockDim.x + threadIdx.x) >> 5;
    const int lane  = threadIdx.x & 31;

    const float4 w0 = ((const float4*)W3)[lane];
    const float4 w1 = ((const float4*)W3)[32 + lane];
    const float b30 = b3[0], b31 = b3[1];

    const int rowbase = gwarp * 8;
    #pragma unroll
    for (int i = 0; i < 8; ++i) {
        const int row = rowbase + i;
        const float4 xv = ((const float4*)(X + (size_t)row * N2))[lane];
        float s0 = xv.x * w0.x + xv.y * w0.y + xv.z * w0.z + xv.w * w0.w;
        float s1 = xv.x * w1.x + xv.y * w1.y + xv.z * w1.z + xv.w * w1.w;
        #pragma unroll
        for (int off = 16; off > 0; off >>= 1) {
            s0 += __shfl_xor_sync(0xFFFFFFFFu, s0, off);
            s1 += __shfl_xor_sync(0xFFFFFFFFu, s1, off);
        }
        if (lane == 0) {
            const float mk = (mask[row] >= 0.5f) ? 1.0f : 0.0f;
            const float v0 = (1.0f / (1.0f + expf(-(s0 + b30)))) * 8.0f + 1.0f;
            const float v1 = (1.0f / (1.0f + expf(-(s1 + b31)))) * 8.0f + 1.0f;
            out[row * 2 + 0] = v0 * mk;
            out[row * 2 + 1] = v1 * mk;
        }
    }
}

// ---------------------------------------------------------------------------
// Launch
// ---------------------------------------------------------------------------
extern "C" void kernel_launch(void* const* d_in, const int* in_sizes, int n_in,
                              void* d_out, int out_size)
{
    const float* hidden = (const float*)d_in[0];
    const int*   spans  = (const int*)d_in[1];
    const float* mask   = (const float*)d_in[2];
    const float* W1     = (const float*)d_in[3];
    const float* b1     = (const float*)d_in[4];
    const float* W2     = (const float*)d_in[5];
    const float* b2     = (const float*)d_in[6];
    const float* W3     = (const float*)d_in[7];
    const float* b3     = (const float*)d_in[8];
    float*       out    = (float*)d_out;

    __half *Ah, *Al, *W1h, *W1l, *W2h, *W2l, *x1h, *x1l;
    float  *x2;
    cudaGetSymbolAddress((void**)&Ah,  g_Ah);
    cudaGetSymbolAddress((void**)&Al,  g_Al);
    cudaGetSymbolAddress((void**)&W1h, g_W1h);
    cudaGetSymbolAddress((void**)&W1l, g_W1l);
    cudaGetSymbolAddress((void**)&W2h, g_W2h);
    cudaGetSymbolAddress((void**)&W2l, g_W2l);
    cudaGetSymbolAddress((void**)&x1h, g_x1h);
    cudaGetSymbolAddress((void**)&x1l, g_x1l);
    cudaGetSymbolAddress((void**)&x2,  g_x2);

    cudaFuncSetAttribute(mma_gemm_kernel,
                         cudaFuncAttributeMaxDynamicSharedMemorySize,
                         GEMM_SMEM_BYTES);

    // 0) weight prep
    prep_w_kernel<<<(N1 * K1 + 255) / 256, 256>>>(W1, W2);

    // 1) pooling + pair features (fp16 hi/lo)
    pool_pair_kernel<<<BQ, 256>>>(hidden, spans);

    // 2) layer 1: x1 = gelu(hpair @ W1^T + b1), split fp16 output
    {
        dim3 grid(N1 / 128, BQ / 64);   // (2, 64) = 128 CTAs
        mma_gemm_kernel<<<grid, 256, GEMM_SMEM_BYTES>>>(
            Ah, Al, W1h, W1l, K1, K1, K1, b1,
            nullptr, x1h, x1l, N1, 1);
    }

    // 3) layer 2: x2 = gelu(x1 @ W2^T + b2), fp32 output
    {
        dim3 grid(N2 / 128, BQ / 64);   // (1, 64) = 64 CTAs
        mma_gemm_kernel<<<grid, 256, GEMM_SMEM_BYTES>>>(
            x1h, x1l, W2h, W2l, N1, N1, N1, b2,
            x2, nullptr, nullptr, N2, 0);
    }

    // 4) head
    head_kernel<<<64, 256>>>(x2, W3, b3, mask, out);
}

// round 6
// speedup vs baseline: 2.3012x; 1.0407x over previous
#include <cuda_runtime.h>
#include <cuda_fp16.h>
#include <math.h>
#include <stdint.h>

// Problem constants
#define BB   32
#define LL   512
#define HH   1024
#define QQ   128
#define BQ   (BB * QQ)        // 4096 pair rows
#define K1   (3 * HH)          // 3072
#define N1   256               // VA_H
#define N2   128               // VA_H/2

// Scratch (static device globals)
__device__ __half g_Ah[(size_t)BQ * K1];
__device__ __half g_Al[(size_t)BQ * K1];
__device__ __half g_W1h[(size_t)N1 * K1];
__device__ __half g_W1l[(size_t)N1 * K1];
__device__ __half g_W2h[(size_t)N2 * N1];
__device__ __half g_W2l[(size_t)N2 * N1];
__device__ __half g_x1h[(size_t)BQ * N1];
__device__ __half g_x1l[(size_t)BQ * N1];
__device__ float  g_x2[(size_t)BQ * N2];

// ---------------------------------------------------------------------------
// helpers
// ---------------------------------------------------------------------------
__device__ __forceinline__ uint32_t smem_u32(const void* p) {
    uint32_t a;
    asm("{ .reg .u64 t; cvta.to.shared.u64 t, %1; cvt.u32.u64 %0, t; }"
        : "=r"(a) : "l"(p));
    return a;
}

#define CP_ASYNC16(dst, src) \
    asm volatile("cp.async.cg.shared.global [%0], [%1], 16;" :: "r"(dst), "l"(src) : "memory")
#define CP_COMMIT() asm volatile("cp.async.commit_group;" ::: "memory")
#define CP_WAIT0()  asm volatile("cp.async.wait_group 0;" ::: "memory")
#define CP_WAIT1()  asm volatile("cp.async.wait_group 1;" ::: "memory")

__device__ __forceinline__ void mma16816(float c[4],
                                         const uint32_t a[4],
                                         const uint32_t b[2])
{
    asm volatile(
        "mma.sync.aligned.m16n8k16.row.col.f32.f16.f16.f32 "
        "{%0,%1,%2,%3}, {%4,%5,%6,%7}, {%8,%9}, {%0,%1,%2,%3};\n"
        : "+f"(c[0]), "+f"(c[1]), "+f"(c[2]), "+f"(c[3])
        : "r"(a[0]), "r"(a[1]), "r"(a[2]), "r"(a[3]),
          "r"(b[0]), "r"(b[1]));
}

__device__ __forceinline__ void ldsm4(uint32_t r[4], uint32_t addr)
{
    asm volatile("ldmatrix.sync.aligned.m8n8.x4.shared.b16 {%0,%1,%2,%3}, [%4];"
        : "=r"(r[0]), "=r"(r[1]), "=r"(r[2]), "=r"(r[3]) : "r"(addr));
}

__device__ __forceinline__ float gelu_exact(float x) {
    return 0.5f * x * (1.0f + erff(x * 0.70710678118654752f));
}

// ---------------------------------------------------------------------------
// Weight prep: split W1 and W2 into fp16 hi/lo
// ---------------------------------------------------------------------------
__global__ void prep_w_kernel(const float* __restrict__ W1,
                              const float* __restrict__ W2)
{
    const int i = blockIdx.x * blockDim.x + threadIdx.x;
    if (i < N1 * K1) {
        const float v  = W1[i];
        const __half h = __float2half_rn(v);
        g_W1h[i] = h;
        g_W1l[i] = __float2half_rn(v - __half2float(h));
    }
    if (i < N2 * N1) {
        const float v  = W2[i];
        const __half h = __float2half_rn(v);
        g_W2h[i] = h;
        g_W2l[i] = __float2half_rn(v - __half2float(h));
    }
}

// ---------------------------------------------------------------------------
// Span pooling + pair features (fp16 hi/lo), float4 loads, half4 stores.
// ---------------------------------------------------------------------------
__device__ __forceinline__ void split_store4(__half* hi, __half* lo,
                                             size_t idx, float4 v)
{
    const __half h0 = __float2half_rn(v.x);
    const __half h1 = __float2half_rn(v.y);
    const __half h2 = __float2half_rn(v.z);
    const __half h3 = __float2half_rn(v.w);
    __half2 hh[2] = { __halves2half2(h0, h1), __halves2half2(h2, h3) };
    __half2 ll[2] = {
        __halves2half2(__float2half_rn(v.x - __half2float(h0)),
                       __float2half_rn(v.y - __half2float(h1))),
        __halves2half2(__float2half_rn(v.z - __half2float(h2)),
                       __float2half_rn(v.w - __half2float(h3))) };
    *(uint2*)(hi + idx) = *(uint2*)hh;
    *(uint2*)(lo + idx) = *(uint2*)ll;
}

__global__ void pool_pair_kernel(const float* __restrict__ hs,
                                 const int* __restrict__ spans)
{
    const int bq  = blockIdx.x;
    const int b   = bq >> 7;
    const int tid = threadIdx.x;

    const int* sp = spans + (size_t)bq * 4;
    const int as = sp[0], ae = sp[1], os = sp[2], oe = sp[3];
    const bool av = (as >= 2) && (ae >= as);
    const bool ov = (os >= 2) && (oe >= os);

    const float* base = hs + (size_t)b * LL * HH + 4 * tid;

    float4 aacc = {0.f, 0.f, 0.f, 0.f};
    float4 oacc = {0.f, 0.f, 0.f, 0.f};

    {
        int s = av ? as : 1, e = av ? ae : 1;
        s = min(max(s, 0), LL - 1);
        e = min(max(e, 0), LL - 1);
        const float inv = 1.0f / (float)((e - s + 1) > 0 ? (e - s + 1) : 1);
        for (int r = s; r <= e; ++r) {
            const float4 v = *(const float4*)(base + (size_t)r * HH);
            aacc.x += v.x; aacc.y += v.y; aacc.z += v.z; aacc.w += v.w;
        }
        aacc.x *= inv; aacc.y *= inv; aacc.z *= inv; aacc.w *= inv;
    }
    {
        int s = ov ? os : 1, e = ov ? oe : 1;
        s = min(max(s, 0), LL - 1);
        e = min(max(e, 0), LL - 1);
        const float inv = 1.0f / (float)((e - s + 1) > 0 ? (e - s + 1) : 1);
        for (int r = s; r <= e; ++r) {
            const float4 v = *(const float4*)(base + (size_t)r * HH);
            oacc.x += v.x; oacc.y += v.y; oacc.z += v.z; oacc.w += v.w;
        }
        oacc.x *= inv; oacc.y *= inv; oacc.z *= inv; oacc.w *= inv;
    }

    float4 pacc;
    pacc.x = aacc.x * oacc.x;  pacc.y = aacc.y * oacc.y;
    pacc.z = aacc.z * oacc.z;  pacc.w = aacc.w * oacc.w;

    const size_t rowoff = (size_t)bq * K1 + 4 * tid;
    split_store4(g_Ah, g_Al, rowoff,           aacc);
    split_store4(g_Ah, g_Al, rowoff + HH,      oacc);
    split_store4(g_Ah, g_Al, rowoff + 2 * HH,  pacc);
}

// ---------------------------------------------------------------------------
// Pipelined mma.sync GEMM with fp16 hi/lo split (3 passes, fp32 accum),
// ldmatrix.x4 fragment loads. BM=64, BN=64*NTP, BK=32, 256 threads = 8 warps
// (2M x 4N). 2-stage cp.async double buffering.
// mode 0: out_f = gelu(acc+bias);  mode 1: gelu(acc+bias) split to out_h/out_l
// smem row: 32 halves = 16 data words + 4 pad = 20 words (80 B) -> ldmatrix
// rows land on distinct 16B offsets mod 128 (conflict-free).
// ---------------------------------------------------------------------------
template<int NTP>
__global__ __launch_bounds__(256)
void mma_gemm_kernel(const __half* __restrict__ Ah, const __half* __restrict__ Al,
                     const __half* __restrict__ Bh, const __half* __restrict__ Bl,
                     int lda, int ldb, int K,
                     const float* __restrict__ bias,
                     float* __restrict__ out_f,
                     __half* __restrict__ out_h, __half* __restrict__ out_l,
                     int out_ld, int mode)
{
    constexpr int BN    = 64 * NTP;
    constexpr int AWd   = 64 * 20;          // words per A buffer
    constexpr int BWd   = BN * 20;          // words per B buffer
    constexpr int STWd  = 2 * AWd + 2 * BWd;
    constexpr int UNITS = (512 + BN * 8) / 256;   // 16B chunks per thread

    extern __shared__ uint32_t sm[];
    const uint32_t smem32 = smem_u32(sm);

    const int tid   = threadIdx.x;
    const int warp  = tid >> 5;
    const int lane  = tid & 31;
    const int warpM = warp >> 2;
    const int warpN = warp & 3;
    const int lane4 = lane >> 2;
    const int lanem = lane & 3;

    const int m0 = blockIdx.y * 64;
    const int n0 = blockIdx.x * BN;
    const int nk = K >> 5;

    // lane-dependent ldmatrix byte offsets
    const uint32_t aLaneOff = ((lane & 15) * 20 + ((lane >> 4) << 2)) * 4;
    const uint32_t bLaneOff = (((lane & 7) + ((lane >> 4) << 3)) * 20
                               + (((lane >> 3) & 1) << 2)) * 4;
    const uint32_t aWarpOff = (uint32_t)(warpM * 32) * 80;          // rows*20w*4B
    const uint32_t bWarpOff = (uint32_t)(warpN * (NTP * 16)) * 80;

    auto load_stage = [&](int c) {
        const uint32_t sb = smem32 + (uint32_t)(c & 1) * (STWd * 4);
        const int kk = c * 32;
        #pragma unroll
        for (int i = 0; i < UNITS; ++i) {
            const int u = i * 256 + tid;
            const __half* src;
            uint32_t dstw;
            if (u < 512) {
                const int hsel = u >> 8;
                const int v = u & 255;
                const int row = v >> 2, seg = v & 3;
                src  = (hsel ? Al : Ah) + (size_t)(m0 + row) * lda + kk + seg * 8;
                dstw = (hsel ? AWd : 0) + row * 20 + seg * 4;
            } else {
                const int v = u - 512;
                const int hsel = v / (BN * 4);
                const int w = v % (BN * 4);
                const int row = w >> 2, seg = w & 3;
                src  = (hsel ? Bl : Bh) + (size_t)(n0 + row) * ldb + kk + seg * 8;
                dstw = 2 * AWd + (hsel ? BWd : 0) + row * 20 + seg * 4;
            }
            CP_ASYNC16(sb + dstw * 4, src);
        }
        CP_COMMIT();
    };

    float acc[2][2 * NTP][4];
    #pragma unroll
    for (int i = 0; i < 2; ++i)
        #pragma unroll
        for (int j = 0; j < 2 * NTP; ++j)
            #pragma unroll
            for (int k = 0; k < 4; ++k) acc[i][j][k] = 0.f;

    load_stage(0);

    for (int c = 0; c < nk; ++c) {
        if (c + 1 < nk) { load_stage(c + 1); CP_WAIT1(); }
        else            { CP_WAIT0(); }
        __syncthreads();

        const uint32_t sb = smem32 + (uint32_t)(c & 1) * (STWd * 4);
        const uint32_t aB = sb + aWarpOff + aLaneOff;
        const uint32_t bB = sb + 2 * AWd * 4 + bWarpOff + bLaneOff;

        #pragma unroll
        for (int sub = 0; sub < 2; ++sub) {
            uint32_t ah[2][4], al[2][4];
            #pragma unroll
            for (int mt = 0; mt < 2; ++mt) {
                ldsm4(ah[mt], aB + (uint32_t)mt * (16 * 80) + sub * 32);
                ldsm4(al[mt], aB + AWd * 4 + (uint32_t)mt * (16 * 80) + sub * 32);
            }
            #pragma unroll
            for (int ntp = 0; ntp < NTP; ++ntp) {
                uint32_t bh[4], bl[4];
                ldsm4(bh, bB + (uint32_t)ntp * (16 * 80) + sub * 32);
                ldsm4(bl, bB + BWd * 4 + (uint32_t)ntp * (16 * 80) + sub * 32);
                #pragma unroll
                for (int hf = 0; hf < 2; ++hf) {
                    const int nt = ntp * 2 + hf;
                    const uint32_t* bph = bh + hf * 2;
                    const uint32_t* bpl = bl + hf * 2;
                    #pragma unroll
                    for (int mt = 0; mt < 2; ++mt) {
                        mma16816(acc[mt][nt], ah[mt], bph);
                        mma16816(acc[mt][nt], ah[mt], bpl);
                        mma16816(acc[mt][nt], al[mt], bph);
                    }
                }
            }
        }
        __syncthreads();
    }

    // ---- epilogue: bias + gelu (+ optional fp16 split) ----
    #pragma unroll
    for (int mt = 0; mt < 2; ++mt) {
        #pragma unroll
        for (int nt = 0; nt < 2 * NTP; ++nt) {
            const int c0 = n0 + warpN * (NTP * 16) + nt * 8 + lanem * 2;
            const float bv0 = bias[c0];
            const float bv1 = bias[c0 + 1];
            const int r0 = m0 + warpM * 32 + mt * 16 + lane4;

            const float g00 = gelu_exact(acc[mt][nt][0] + bv0);
            const float g01 = gelu_exact(acc[mt][nt][1] + bv1);
            const float g10 = gelu_exact(acc[mt][nt][2] + bv0);
            const float g11 = gelu_exact(acc[mt][nt][3] + bv1);

            if (mode == 0) {
                *(float2*)(out_f + (size_t)r0 * out_ld + c0)       = make_float2(g00, g01);
                *(float2*)(out_f + (size_t)(r0 + 8) * out_ld + c0) = make_float2(g10, g11);
            } else {
                const __half h00 = __float2half_rn(g00), h01 = __float2half_rn(g01);
                const __half h10 = __float2half_rn(g10), h11 = __float2half_rn(g11);
                __half2 v0h = __halves2half2(h00, h01);
                __half2 v1h = __halves2half2(h10, h11);
                __half2 v0l = __halves2half2(__float2half_rn(g00 - __half2float(h00)),
                                             __float2half_rn(g01 - __half2float(h01)));
                __half2 v1l = __halves2half2(__float2half_rn(g10 - __half2float(h10)),
                                             __float2half_rn(g11 - __half2float(h11)));
                *(__half2*)(out_h + (size_t)r0 * out_ld + c0)       = v0h;
                *(__half2*)(out_h + (size_t)(r0 + 8) * out_ld + c0) = v1h;
                *(__half2*)(out_l + (size_t)r0 * out_ld + c0)       = v0l;
                *(__half2*)(out_l + (size_t)(r0 + 8) * out_ld + c0) = v1l;
            }
        }
    }
}

#define GEMM1_SMEM ((2 * (2 * 64 * 20 + 2 * 128 * 20)) * 4)   // 61440 B
#define GEMM2_SMEM ((2 * (2 * 64 * 20 + 2 *  64 * 20)) * 4)   // 40960 B

// ---------------------------------------------------------------------------
// Head: one warp per 8 rows, shuffle reduction over K=128
// ---------------------------------------------------------------------------
__global__ void head_kernel(const float* __restrict__ X,
                            const float* __restrict__ W3,
                            const float* __restrict__ b3,
                            const float* __restrict__ mask,
                            float* __restrict__ out)
{
    const int gwarp = (blockIdx.x * blockDim.x + threadIdx.x) >> 5;
    const int lane  = threadIdx.x & 31;

    const float4 w0 = ((const float4*)W3)[lane];
    const float4 w1 = ((const float4*)W3)[32 + lane];
    const float b30 = b3[0], b31 = b3[1];

    const int rowbase = gwarp * 8;
    #pragma unroll
    for (int i = 0; i < 8; ++i) {
        const int row = rowbase + i;
        const float4 xv = ((const float4*)(X + (size_t)row * N2))[lane];
        float s0 = xv.x * w0.x + xv.y * w0.y + xv.z * w0.z + xv.w * w0.w;
        float s1 = xv.x * w1.x + xv.y * w1.y + xv.z * w1.z + xv.w * w1.w;
        #pragma unroll
        for (int off = 16; off > 0; off >>= 1) {
            s0 += __shfl_xor_sync(0xFFFFFFFFu, s0, off);
            s1 += __shfl_xor_sync(0xFFFFFFFFu, s1, off);
        }
        if (lane == 0) {
            const float mk = (mask[row] >= 0.5f) ? 1.0f : 0.0f;
            const float v0 = (1.0f / (1.0f + expf(-(s0 + b30)))) * 8.0f + 1.0f;
            const float v1 = (1.0f / (1.0f + expf(-(s1 + b31)))) * 8.0f + 1.0f;
            out[row * 2 + 0] = v0 * mk;
            out[row * 2 + 1] = v1 * mk;
        }
    }
}

// ---------------------------------------------------------------------------
// Launch
// ---------------------------------------------------------------------------
extern "C" void kernel_launch(void* const* d_in, const int* in_sizes, int n_in,
                              void* d_out, int out_size)
{
    const float* hidden = (const float*)d_in[0];
    const int*   spans  = (const int*)d_in[1];
    const float* mask   = (const float*)d_in[2];
    const float* W1     = (const float*)d_in[3];
    const float* b1     = (const float*)d_in[4];
    const float* W2     = (const float*)d_in[5];
    const float* b2     = (const float*)d_in[6];
    const float* W3     = (const float*)d_in[7];
    const float* b3     = (const float*)d_in[8];
    float*       out    = (float*)d_out;

    __half *Ah, *Al, *W1h, *W1l, *W2h, *W2l, *x1h, *x1l;
    float  *x2;
    cudaGetSymbolAddress((void**)&Ah,  g_Ah);
    cudaGetSymbolAddress((void**)&Al,  g_Al);
    cudaGetSymbolAddress((void**)&W1h, g_W1h);
    cudaGetSymbolAddress((void**)&W1l, g_W1l);
    cudaGetSymbolAddress((void**)&W2h, g_W2h);
    cudaGetSymbolAddress((void**)&W2l, g_W2l);
    cudaGetSymbolAddress((void**)&x1h, g_x1h);
    cudaGetSymbolAddress((void**)&x1l, g_x1l);
    cudaGetSymbolAddress((void**)&x2,  g_x2);

    cudaFuncSetAttribute(mma_gemm_kernel<2>,
                         cudaFuncAttributeMaxDynamicSharedMemorySize, GEMM1_SMEM);
    cudaFuncSetAttribute(mma_gemm_kernel<1>,
                         cudaFuncAttributeMaxDynamicSharedMemorySize, GEMM2_SMEM);

    // 0) weight prep
    prep_w_kernel<<<(N1 * K1 + 255) / 256, 256>>>(W1, W2);

    // 1) pooling + pair features (fp16 hi/lo)
    pool_pair_kernel<<<BQ, 256>>>(hidden, spans);

    // 2) layer 1: x1 = gelu(hpair @ W1^T + b1), split fp16 output
    {
        dim3 grid(N1 / 128, BQ / 64);   // (2, 64) = 128 CTAs
        mma_gemm_kernel<2><<<grid, 256, GEMM1_SMEM>>>(
            Ah, Al, W1h, W1l, K1, K1, K1, b1,
            nullptr, x1h, x1l, N1, 1);
    }

    // 3) layer 2: x2 = gelu(x1 @ W2^T + b2), fp32 output
    {
        dim3 grid(N2 / 64, BQ / 64);    // (2, 64) = 128 CTAs
        mma_gemm_kernel<1><<<grid, 256, GEMM2_SMEM>>>(
            x1h, x1l, W2h, W2l, N1, N1, N1, b2,
            x2, nullptr, nullptr, N2, 0);
    }

    // 4) head
    head_kernel<<<64, 256>>>(x2, W3, b3, mask, out);
}

// round 7
// speedup vs baseline: 2.5732x; 1.1182x over previous
#include <cuda_runtime.h>
#include <cuda_fp16.h>
#include <math.h>
#include <stdint.h>

// Problem constants
#define BB   32
#define LL   512
#define HH   1024
#define QQ   128
#define BQ   (BB * QQ)        // 4096 pair rows
#define K1   (3 * HH)          // 3072
#define N1   256               // VA_H
#define N2   128               // VA_H/2

// Scratch (static device globals)
__device__ __half g_Ah[(size_t)BQ * K1];
__device__ __half g_Al[(size_t)BQ * K1];
__device__ __half g_W1h[(size_t)N1 * K1];
__device__ __half g_W1l[(size_t)N1 * K1];
__device__ __half g_W2h[(size_t)N2 * N1];
__device__ __half g_W2l[(size_t)N2 * N1];
__device__ float  g_part[(size_t)2 * BQ * N1];   // K-split partials, 8 MB
__device__ __half g_x1h[(size_t)BQ * N1];
__device__ __half g_x1l[(size_t)BQ * N1];
__device__ float  g_x2[(size_t)BQ * N2];

// ---------------------------------------------------------------------------
// helpers
// ---------------------------------------------------------------------------
__device__ __forceinline__ uint32_t smem_u32(const void* p) {
    uint32_t a;
    asm("{ .reg .u64 t; cvta.to.shared.u64 t, %1; cvt.u32.u64 %0, t; }"
        : "=r"(a) : "l"(p));
    return a;
}

#define CP_ASYNC16(dst, src) \
    asm volatile("cp.async.cg.shared.global [%0], [%1], 16;" :: "r"(dst), "l"(src) : "memory")
#define CP_COMMIT() asm volatile("cp.async.commit_group;" ::: "memory")
#define CP_WAIT0()  asm volatile("cp.async.wait_group 0;" ::: "memory")
#define CP_WAIT1()  asm volatile("cp.async.wait_group 1;" ::: "memory")

__device__ __forceinline__ void mma16816(float c[4],
                                         const uint32_t a[4],
                                         const uint32_t b[2])
{
    asm volatile(
        "mma.sync.aligned.m16n8k16.row.col.f32.f16.f16.f32 "
        "{%0,%1,%2,%3}, {%4,%5,%6,%7}, {%8,%9}, {%0,%1,%2,%3};\n"
        : "+f"(c[0]), "+f"(c[1]), "+f"(c[2]), "+f"(c[3])
        : "r"(a[0]), "r"(a[1]), "r"(a[2]), "r"(a[3]),
          "r"(b[0]), "r"(b[1]));
}

__device__ __forceinline__ void ldsm4(uint32_t r[4], uint32_t addr)
{
    asm volatile("ldmatrix.sync.aligned.m8n8.x4.shared.b16 {%0,%1,%2,%3}, [%4];"
        : "=r"(r[0]), "=r"(r[1]), "=r"(r[2]), "=r"(r[3]) : "r"(addr));
}

__device__ __forceinline__ float gelu_exact(float x) {
    return 0.5f * x * (1.0f + erff(x * 0.70710678118654752f));
}

// ---------------------------------------------------------------------------
// Weight prep: split W1 and W2 into fp16 hi/lo
// ---------------------------------------------------------------------------
__global__ void prep_w_kernel(const float* __restrict__ W1,
                              const float* __restrict__ W2)
{
    const int i = blockIdx.x * blockDim.x + threadIdx.x;
    if (i < N1 * K1) {
        const float v  = W1[i];
        const __half h = __float2half_rn(v);
        g_W1h[i] = h;
        g_W1l[i] = __float2half_rn(v - __half2float(h));
    }
    if (i < N2 * N1) {
        const float v  = W2[i];
        const __half h = __float2half_rn(v);
        g_W2h[i] = h;
        g_W2l[i] = __float2half_rn(v - __half2float(h));
    }
}

// ---------------------------------------------------------------------------
// Span pooling + pair features (fp16 hi/lo)
// ---------------------------------------------------------------------------
__device__ __forceinline__ void split_store4(__half* hi, __half* lo,
                                             size_t idx, float4 v)
{
    const __half h0 = __float2half_rn(v.x);
    const __half h1 = __float2half_rn(v.y);
    const __half h2 = __float2half_rn(v.z);
    const __half h3 = __float2half_rn(v.w);
    __half2 hh[2] = { __halves2half2(h0, h1), __halves2half2(h2, h3) };
    __half2 ll[2] = {
        __halves2half2(__float2half_rn(v.x - __half2float(h0)),
                       __float2half_rn(v.y - __half2float(h1))),
        __halves2half2(__float2half_rn(v.z - __half2float(h2)),
                       __float2half_rn(v.w - __half2float(h3))) };
    *(uint2*)(hi + idx) = *(uint2*)hh;
    *(uint2*)(lo + idx) = *(uint2*)ll;
}

__global__ void pool_pair_kernel(const float* __restrict__ hs,
                                 const int* __restrict__ spans)
{
    const int bq  = blockIdx.x;
    const int b   = bq >> 7;
    const int tid = threadIdx.x;

    const int* sp = spans + (size_t)bq * 4;
    const int as = sp[0], ae = sp[1], os = sp[2], oe = sp[3];
    const bool av = (as >= 2) && (ae >= as);
    const bool ov = (os >= 2) && (oe >= os);

    const float* base = hs + (size_t)b * LL * HH + 4 * tid;

    float4 aacc = {0.f, 0.f, 0.f, 0.f};
    float4 oacc = {0.f, 0.f, 0.f, 0.f};

    {
        int s = av ? as : 1, e = av ? ae : 1;
        s = min(max(s, 0), LL - 1);
        e = min(max(e, 0), LL - 1);
        const float inv = 1.0f / (float)((e - s + 1) > 0 ? (e - s + 1) : 1);
        for (int r = s; r <= e; ++r) {
            const float4 v = *(const float4*)(base + (size_t)r * HH);
            aacc.x += v.x; aacc.y += v.y; aacc.z += v.z; aacc.w += v.w;
        }
        aacc.x *= inv; aacc.y *= inv; aacc.z *= inv; aacc.w *= inv;
    }
    {
        int s = ov ? os : 1, e = ov ? oe : 1;
        s = min(max(s, 0), LL - 1);
        e = min(max(e, 0), LL - 1);
        const float inv = 1.0f / (float)((e - s + 1) > 0 ? (e - s + 1) : 1);
        for (int r = s; r <= e; ++r) {
            const float4 v = *(const float4*)(base + (size_t)r * HH);
            oacc.x += v.x; oacc.y += v.y; oacc.z += v.z; oacc.w += v.w;
        }
        oacc.x *= inv; oacc.y *= inv; oacc.z *= inv; oacc.w *= inv;
    }

    float4 pacc;
    pacc.x = aacc.x * oacc.x;  pacc.y = aacc.y * oacc.y;
    pacc.z = aacc.z * oacc.z;  pacc.w = aacc.w * oacc.w;

    const size_t rowoff = (size_t)bq * K1 + 4 * tid;
    split_store4(g_Ah, g_Al, rowoff,           aacc);
    split_store4(g_Ah, g_Al, rowoff + HH,      oacc);
    split_store4(g_Ah, g_Al, rowoff + 2 * HH,  pacc);
}

// ---------------------------------------------------------------------------
// Pipelined mma.sync GEMM, fp16 hi/lo split (3 passes, fp32 accum), ldmatrix.
// BM=32*MTP, BN=64*NTP, BK=32, 256 threads = 8 warps (2M x 4N).
// 2-stage cp.async. K-split via blockIdx.z (kslice per z, mode 2 partials).
// mode 0: out_f = gelu(acc+bias)
// mode 1: gelu(acc+bias) -> fp16 hi/lo (out_h/out_l)
// mode 2: out_f[z] = raw fp32 partial (no bias/gelu)
// ---------------------------------------------------------------------------
template<int MTP, int NTP>
__global__ __launch_bounds__(256)
void mma_gemm_kernel(const __half* __restrict__ Ah, const __half* __restrict__ Al,
                     const __half* __restrict__ Bh, const __half* __restrict__ Bl,
                     int lda, int ldb, int kslice,
                     const float* __restrict__ bias,
                     float* __restrict__ out_f,
                     __half* __restrict__ out_h, __half* __restrict__ out_l,
                     int out_ld, int mode, size_t zstride)
{
    constexpr int BM    = 32 * MTP;
    constexpr int BN    = 64 * NTP;
    constexpr int AWd   = BM * 20;          // words per A buffer
    constexpr int BWd   = BN * 20;          // words per B buffer
    constexpr int STWd  = 2 * AWd + 2 * BWd;
    constexpr int UNITS = (BM + BN) * 8 / 256;   // 16B chunks per thread

    extern __shared__ uint32_t sm[];
    const uint32_t smem32 = smem_u32(sm);

    const int tid   = threadIdx.x;
    const int warp  = tid >> 5;
    const int lane  = tid & 31;
    const int warpM = warp >> 2;
    const int warpN = warp & 3;
    const int lane4 = lane >> 2;
    const int lanem = lane & 3;

    const int m0    = blockIdx.y * BM;
    const int n0    = blockIdx.x * BN;
    const int kbase = blockIdx.z * kslice;
    const int nk    = kslice >> 5;

    const uint32_t aLaneOff = ((lane & 15) * 20 + ((lane >> 4) << 2)) * 4;
    const uint32_t bLaneOff = (((lane & 7) + ((lane >> 4) << 3)) * 20
                               + (((lane >> 3) & 1) << 2)) * 4;
    const uint32_t aWarpOff = (uint32_t)(warpM * (16 * MTP)) * 80;
    const uint32_t bWarpOff = (uint32_t)(warpN * (NTP * 16)) * 80;

    auto load_stage = [&](int c) {
        const uint32_t sb = smem32 + (uint32_t)(c & 1) * (STWd * 4);
        const int kk = kbase + c * 32;
        #pragma unroll
        for (int i = 0; i < UNITS; ++i) {
            const int u = i * 256 + tid;
            const __half* src;
            uint32_t dstw;
            if (u < BM * 8) {
                const int hsel = u >= BM * 4;
                const int v = u & (BM * 4 - 1);
                const int row = v >> 2, seg = v & 3;
                src  = (hsel ? Al : Ah) + (size_t)(m0 + row) * lda + kk + seg * 8;
                dstw = (hsel ? AWd : 0) + row * 20 + seg * 4;
            } else {
                const int v = u - BM * 8;
                const int hsel = v / (BN * 4);
                const int w = v % (BN * 4);
                const int row = w >> 2, seg = w & 3;
                src  = (hsel ? Bl : Bh) + (size_t)(n0 + row) * ldb + kk + seg * 8;
                dstw = 2 * AWd + (hsel ? BWd : 0) + row * 20 + seg * 4;
            }
            CP_ASYNC16(sb + dstw * 4, src);
        }
        CP_COMMIT();
    };

    float acc[MTP][2 * NTP][4];
    #pragma unroll
    for (int i = 0; i < MTP; ++i)
        #pragma unroll
        for (int j = 0; j < 2 * NTP; ++j)
            #pragma unroll
            for (int k = 0; k < 4; ++k) acc[i][j][k] = 0.f;

    load_stage(0);

    for (int c = 0; c < nk; ++c) {
        if (c + 1 < nk) { load_stage(c + 1); CP_WAIT1(); }
        else            { CP_WAIT0(); }
        __syncthreads();

        const uint32_t sb = smem32 + (uint32_t)(c & 1) * (STWd * 4);
        const uint32_t aB = sb + aWarpOff + aLaneOff;
        const uint32_t bB = sb + 2 * AWd * 4 + bWarpOff + bLaneOff;

        #pragma unroll
        for (int sub = 0; sub < 2; ++sub) {
            uint32_t ah[MTP][4], al[MTP][4];
            #pragma unroll
            for (int mt = 0; mt < MTP; ++mt) {
                ldsm4(ah[mt], aB + (uint32_t)mt * (16 * 80) + sub * 32);
                ldsm4(al[mt], aB + AWd * 4 + (uint32_t)mt * (16 * 80) + sub * 32);
            }
            #pragma unroll
            for (int ntp = 0; ntp < NTP; ++ntp) {
                uint32_t bh[4], bl[4];
                ldsm4(bh, bB + (uint32_t)ntp * (16 * 80) + sub * 32);
                ldsm4(bl, bB + BWd * 4 + (uint32_t)ntp * (16 * 80) + sub * 32);
                #pragma unroll
                for (int hf = 0; hf < 2; ++hf) {
                    const int nt = ntp * 2 + hf;
                    const uint32_t* bph = bh + hf * 2;
                    const uint32_t* bpl = bl + hf * 2;
                    #pragma unroll
                    for (int mt = 0; mt < MTP; ++mt) {
                        mma16816(acc[mt][nt], ah[mt], bph);
                        mma16816(acc[mt][nt], ah[mt], bpl);
                        mma16816(acc[mt][nt], al[mt], bph);
                    }
                }
            }
        }
        __syncthreads();
    }

    // ---- epilogue ----
    float* out_fz = out_f ? out_f + (size_t)blockIdx.z * zstride : nullptr;

    #pragma unroll
    for (int mt = 0; mt < MTP; ++mt) {
        #pragma unroll
        for (int nt = 0; nt < 2 * NTP; ++nt) {
            const int c0 = n0 + warpN * (NTP * 16) + nt * 8 + lanem * 2;
            const int r0 = m0 + warpM * (16 * MTP) + mt * 16 + lane4;

            if (mode == 2) {
                *(float2*)(out_fz + (size_t)r0 * out_ld + c0) =
                    make_float2(acc[mt][nt][0], acc[mt][nt][1]);
                *(float2*)(out_fz + (size_t)(r0 + 8) * out_ld + c0) =
                    make_float2(acc[mt][nt][2], acc[mt][nt][3]);
                continue;
            }

            const float bv0 = bias[c0];
            const float bv1 = bias[c0 + 1];
            const float g00 = gelu_exact(acc[mt][nt][0] + bv0);
            const float g01 = gelu_exact(acc[mt][nt][1] + bv1);
            const float g10 = gelu_exact(acc[mt][nt][2] + bv0);
            const float g11 = gelu_exact(acc[mt][nt][3] + bv1);

            if (mode == 0) {
                *(float2*)(out_fz + (size_t)r0 * out_ld + c0)       = make_float2(g00, g01);
                *(float2*)(out_fz + (size_t)(r0 + 8) * out_ld + c0) = make_float2(g10, g11);
            } else {
                const __half h00 = __float2half_rn(g00), h01 = __float2half_rn(g01);
                const __half h10 = __float2half_rn(g10), h11 = __float2half_rn(g11);
                __half2 v0h = __halves2half2(h00, h01);
                __half2 v1h = __halves2half2(h10, h11);
                __half2 v0l = __halves2half2(__float2half_rn(g00 - __half2float(h00)),
                                             __float2half_rn(g01 - __half2float(h01)));
                __half2 v1l = __halves2half2(__float2half_rn(g10 - __half2float(h10)),
                                             __float2half_rn(g11 - __half2float(h11)));
                *(__half2*)(out_h + (size_t)r0 * out_ld + c0)       = v0h;
                *(__half2*)(out_h + (size_t)(r0 + 8) * out_ld + c0) = v1h;
                *(__half2*)(out_l + (size_t)r0 * out_ld + c0)       = v0l;
                *(__half2*)(out_l + (size_t)(r0 + 8) * out_ld + c0) = v1l;
            }
        }
    }
}

#define GEMM1_SMEM ((2 * (2 * 64 * 20 + 2 * 128 * 20)) * 4)   // 61440 B
#define GEMM2_SMEM ((2 * (2 * 32 * 20 + 2 *  64 * 20)) * 4)   // 30720 B

// ---------------------------------------------------------------------------
// Combine K-split partials: x1 = gelu(p0 + p1 + b1) -> fp16 hi/lo
// ---------------------------------------------------------------------------
__global__ void combine_kernel(const float* __restrict__ b1)
{
    const int idx = blockIdx.x * blockDim.x + threadIdx.x;   // float4 index
    const float4 p0 = ((const float4*)g_part)[idx];
    const float4 p1 = ((const float4*)g_part)[idx + (BQ * N1) / 4];
    const float4 bv = ((const float4*)b1)[idx & (N1 / 4 - 1)];
    float4 g;
    g.x = gelu_exact(p0.x + p1.x + bv.x);
    g.y = gelu_exact(p0.y + p1.y + bv.y);
    g.z = gelu_exact(p0.z + p1.z + bv.z);
    g.w = gelu_exact(p0.w + p1.w + bv.w);
    split_store4(g_x1h, g_x1l, (size_t)idx * 4, g);
}

// ---------------------------------------------------------------------------
// Head: one warp per 8 rows, shuffle reduction over K=128
// ---------------------------------------------------------------------------
__global__ void head_kernel(const float* __restrict__ X,
                            const float* __restrict__ W3,
                            const float* __restrict__ b3,
                            const float* __restrict__ mask,
                            float* __restrict__ out)
{
    const int gwarp = (blockIdx.x * blockDim.x + threadIdx.x) >> 5;
    const int lane  = threadIdx.x & 31;

    const float4 w0 = ((const float4*)W3)[lane];
    const float4 w1 = ((const float4*)W3)[32 + lane];
    const float b30 = b3[0], b31 = b3[1];

    const int rowbase = gwarp * 8;
    #pragma unroll
    for (int i = 0; i < 8; ++i) {
        const int row = rowbase + i;
        const float4 xv = ((const float4*)(X + (size_t)row * N2))[lane];
        float s0 = xv.x * w0.x + xv.y * w0.y + xv.z * w0.z + xv.w * w0.w;
        float s1 = xv.x * w1.x + xv.y * w1.y + xv.z * w1.z + xv.w * w1.w;
        #pragma unroll
        for (int off = 16; off > 0; off >>= 1) {
            s0 += __shfl_xor_sync(0xFFFFFFFFu, s0, off);
            s1 += __shfl_xor_sync(0xFFFFFFFFu, s1, off);
        }
        if (lane == 0) {
            const float mk = (mask[row] >= 0.5f) ? 1.0f : 0.0f;
            const float v0 = (1.0f / (1.0f + expf(-(s0 + b30)))) * 8.0f + 1.0f;
            const float v1 = (1.0f / (1.0f + expf(-(s1 + b31)))) * 8.0f + 1.0f;
            out[row * 2 + 0] = v0 * mk;
            out[row * 2 + 1] = v1 * mk;
        }
    }
}

// ---------------------------------------------------------------------------
// Launch
// ---------------------------------------------------------------------------
extern "C" void kernel_launch(void* const* d_in, const int* in_sizes, int n_in,
                              void* d_out, int out_size)
{
    const float* hidden = (const float*)d_in[0];
    const int*   spans  = (const int*)d_in[1];
    const float* mask   = (const float*)d_in[2];
    const float* W1     = (const float*)d_in[3];
    const float* b1     = (const float*)d_in[4];
    const float* W2     = (const float*)d_in[5];
    const float* b2     = (const float*)d_in[6];
    const float* W3     = (const float*)d_in[7];
    const float* b3     = (const float*)d_in[8];
    float*       out    = (float*)d_out;

    __half *Ah, *Al, *W1h, *W1l, *W2h, *W2l, *x1h, *x1l;
    float  *part, *x2;
    cudaGetSymbolAddress((void**)&Ah,   g_Ah);
    cudaGetSymbolAddress((void**)&Al,   g_Al);
    cudaGetSymbolAddress((void**)&W1h,  g_W1h);
    cudaGetSymbolAddress((void**)&W1l,  g_W1l);
    cudaGetSymbolAddress((void**)&W2h,  g_W2h);
    cudaGetSymbolAddress((void**)&W2l,  g_W2l);
    cudaGetSymbolAddress((void**)&x1h,  g_x1h);
    cudaGetSymbolAddress((void**)&x1l,  g_x1l);
    cudaGetSymbolAddress((void**)&part, g_part);
    cudaGetSymbolAddress((void**)&x2,   g_x2);

    cudaFuncSetAttribute((const void*)mma_gemm_kernel<2, 2>,
                         cudaFuncAttributeMaxDynamicSharedMemorySize, GEMM1_SMEM);
    cudaFuncSetAttribute((const void*)mma_gemm_kernel<1, 1>,
                         cudaFuncAttributeMaxDynamicSharedMemorySize, GEMM2_SMEM);

    // 0) weight prep
    prep_w_kernel<<<(N1 * K1 + 255) / 256, 256>>>(W1, W2);

    // 1) pooling + pair features (fp16 hi/lo)
    pool_pair_kernel<<<BQ, 256>>>(hidden, spans);

    // 2) layer 1, K-split partials: grid (2, 64, 2) = 256 CTAs
    {
        dim3 grid(N1 / 128, BQ / 64, 2);
        mma_gemm_kernel<2, 2><<<grid, 256, GEMM1_SMEM>>>(
            Ah, Al, W1h, W1l, K1, K1, K1 / 2, nullptr,
            part, nullptr, nullptr, N1, 2, (size_t)BQ * N1);
    }

    // 3) combine partials: bias + gelu + fp16 split
    combine_kernel<<<(BQ * N1 / 4) / 256, 256>>>(b1);

    // 4) layer 2: grid (2, 128) = 256 CTAs, fused bias+gelu, fp32 out
    {
        dim3 grid(N2 / 64, BQ / 32, 1);
        mma_gemm_kernel<1, 1><<<grid, 256, GEMM2_SMEM>>>(
            x1h, x1l, W2h, W2l, N1, N1, N1, b2,
            x2, nullptr, nullptr, N2, 0, 0);
    }

    // 5) head
    head_kernel<<<64, 256>>>(x2, W3, b3, mask, out);
}

// round 8
// speedup vs baseline: 3.1016x; 1.2053x over previous
#include <cuda_runtime.h>
#include <cuda_fp16.h>
#include <math.h>
#include <stdint.h>

// Problem constants
#define BB   32
#define LL   512
#define HH   1024
#define QQ   128
#define BQ   (BB * QQ)        // 4096 pair rows
#define K1   (3 * HH)          // 3072
#define N1   256               // VA_H
#define N2   128               // VA_H/2

// Scratch (static device globals)
__device__ __half g_A[(size_t)BQ * K1];          // pooled pair features, fp16
__device__ __half g_W1h[(size_t)N1 * K1];
__device__ __half g_W1l[(size_t)N1 * K1];
__device__ __half g_W2h[(size_t)N2 * N1];
__device__ __half g_W2l[(size_t)N2 * N1];
__device__ float  g_part[(size_t)2 * BQ * N1];   // K-split partials, 8 MB
__device__ __half g_x1[(size_t)BQ * N1];         // gelu(layer1), fp16
__device__ float  g_x2[(size_t)BQ * N2];

// ---------------------------------------------------------------------------
// helpers
// ---------------------------------------------------------------------------
__device__ __forceinline__ uint32_t smem_u32(const void* p) {
    uint32_t a;
    asm("{ .reg .u64 t; cvta.to.shared.u64 t, %1; cvt.u32.u64 %0, t; }"
        : "=r"(a) : "l"(p));
    return a;
}

#define CP_ASYNC16(dst, src) \
    asm volatile("cp.async.cg.shared.global [%0], [%1], 16;" :: "r"(dst), "l"(src) : "memory")
#define CP_COMMIT() asm volatile("cp.async.commit_group;" ::: "memory")
#define CP_WAIT0()  asm volatile("cp.async.wait_group 0;" ::: "memory")
#define CP_WAIT1()  asm volatile("cp.async.wait_group 1;" ::: "memory")

__device__ __forceinline__ void mma16816(float c[4],
                                         const uint32_t a[4],
                                         const uint32_t b[2])
{
    asm volatile(
        "mma.sync.aligned.m16n8k16.row.col.f32.f16.f16.f32 "
        "{%0,%1,%2,%3}, {%4,%5,%6,%7}, {%8,%9}, {%0,%1,%2,%3};\n"
        : "+f"(c[0]), "+f"(c[1]), "+f"(c[2]), "+f"(c[3])
        : "r"(a[0]), "r"(a[1]), "r"(a[2]), "r"(a[3]),
          "r"(b[0]), "r"(b[1]));
}

__device__ __forceinline__ void ldsm4(uint32_t r[4], uint32_t addr)
{
    asm volatile("ldmatrix.sync.aligned.m8n8.x4.shared.b16 {%0,%1,%2,%3}, [%4];"
        : "=r"(r[0]), "=r"(r[1]), "=r"(r[2]), "=r"(r[3]) : "r"(addr));
}

__device__ __forceinline__ float gelu_exact(float x) {
    return 0.5f * x * (1.0f + erff(x * 0.70710678118654752f));
}

__device__ __forceinline__ void store_h4(__half* dst, size_t idx, float4 v)
{
    __half2 hh[2] = {
        __halves2half2(__float2half_rn(v.x), __float2half_rn(v.y)),
        __halves2half2(__float2half_rn(v.z), __float2half_rn(v.w)) };
    *(uint2*)(dst + idx) = *(uint2*)hh;
}

// ---------------------------------------------------------------------------
// Weight prep: split W1 and W2 into fp16 hi/lo
// ---------------------------------------------------------------------------
__global__ void prep_w_kernel(const float* __restrict__ W1,
                              const float* __restrict__ W2)
{
    const int i = blockIdx.x * blockDim.x + threadIdx.x;
    if (i < N1 * K1) {
        const float v  = W1[i];
        const __half h = __float2half_rn(v);
        g_W1h[i] = h;
        g_W1l[i] = __float2half_rn(v - __half2float(h));
    }
    if (i < N2 * N1) {
        const float v  = W2[i];
        const __half h = __float2half_rn(v);
        g_W2h[i] = h;
        g_W2l[i] = __float2half_rn(v - __half2float(h));
    }
}

// ---------------------------------------------------------------------------
// Span pooling + pair features -> fp16
// ---------------------------------------------------------------------------
__global__ void pool_pair_kernel(const float* __restrict__ hs,
                                 const int* __restrict__ spans)
{
    const int bq  = blockIdx.x;
    const int b   = bq >> 7;
    const int tid = threadIdx.x;

    const int* sp = spans + (size_t)bq * 4;
    const int as = sp[0], ae = sp[1], os = sp[2], oe = sp[3];
    const bool av = (as >= 2) && (ae >= as);
    const bool ov = (os >= 2) && (oe >= os);

    const float* base = hs + (size_t)b * LL * HH + 4 * tid;

    float4 aacc = {0.f, 0.f, 0.f, 0.f};
    float4 oacc = {0.f, 0.f, 0.f, 0.f};

    {
        int s = av ? as : 1, e = av ? ae : 1;
        s = min(max(s, 0), LL - 1);
        e = min(max(e, 0), LL - 1);
        const float inv = 1.0f / (float)((e - s + 1) > 0 ? (e - s + 1) : 1);
        for (int r = s; r <= e; ++r) {
            const float4 v = *(const float4*)(base + (size_t)r * HH);
            aacc.x += v.x; aacc.y += v.y; aacc.z += v.z; aacc.w += v.w;
        }
        aacc.x *= inv; aacc.y *= inv; aacc.z *= inv; aacc.w *= inv;
    }
    {
        int s = ov ? os : 1, e = ov ? oe : 1;
        s = min(max(s, 0), LL - 1);
        e = min(max(e, 0), LL - 1);
        const float inv = 1.0f / (float)((e - s + 1) > 0 ? (e - s + 1) : 1);
        for (int r = s; r <= e; ++r) {
            const float4 v = *(const float4*)(base + (size_t)r * HH);
            oacc.x += v.x; oacc.y += v.y; oacc.z += v.z; oacc.w += v.w;
        }
        oacc.x *= inv; oacc.y *= inv; oacc.z *= inv; oacc.w *= inv;
    }

    float4 pacc;
    pacc.x = aacc.x * oacc.x;  pacc.y = aacc.y * oacc.y;
    pacc.z = aacc.z * oacc.z;  pacc.w = aacc.w * oacc.w;

    const size_t rowoff = (size_t)bq * K1 + 4 * tid;
    store_h4(g_A, rowoff,          aacc);
    store_h4(g_A, rowoff + HH,     oacc);
    store_h4(g_A, rowoff + 2 * HH, pacc);
}

// ---------------------------------------------------------------------------
// Pipelined mma.sync GEMM: A fp16, W split hi/lo (2 passes, fp32 accum),
// ldmatrix fragments. BM=32*MTP, BN=64*NTP, BK=32, 256 threads (2M x 4N warps).
// 2-stage cp.async. K-split via blockIdx.z.
// mode 0: out_f = gelu(acc+bias)  fp32
// mode 2: out_f[z] = raw fp32 partial
// ---------------------------------------------------------------------------
template<int MTP, int NTP>
__global__ __launch_bounds__(256)
void mma_gemm_kernel(const __half* __restrict__ A,
                     const __half* __restrict__ Bh, const __half* __restrict__ Bl,
                     int lda, int ldb, int kslice,
                     const float* __restrict__ bias,
                     float* __restrict__ out_f,
                     int out_ld, int mode, size_t zstride)
{
    constexpr int BM    = 32 * MTP;
    constexpr int BN    = 64 * NTP;
    constexpr int AWd   = BM * 20;          // words per A buffer
    constexpr int BWd   = BN * 20;          // words per B buffer
    constexpr int STWd  = AWd + 2 * BWd;
    constexpr int TOT16 = BM * 4 + BN * 8;  // 16B units per stage
    constexpr int UNITS = (TOT16 + 255) / 256;

    extern __shared__ uint32_t sm[];
    const uint32_t smem32 = smem_u32(sm);

    const int tid   = threadIdx.x;
    const int warp  = tid >> 5;
    const int lane  = tid & 31;
    const int warpM = warp >> 2;
    const int warpN = warp & 3;
    const int lane4 = lane >> 2;
    const int lanem = lane & 3;

    const int m0    = blockIdx.y * BM;
    const int n0    = blockIdx.x * BN;
    const int kbase = blockIdx.z * kslice;
    const int nk    = kslice >> 5;

    const uint32_t aLaneOff = ((lane & 15) * 20 + ((lane >> 4) << 2)) * 4;
    const uint32_t bLaneOff = (((lane & 7) + ((lane >> 4) << 3)) * 20
                               + (((lane >> 3) & 1) << 2)) * 4;
    const uint32_t aWarpOff = (uint32_t)(warpM * (16 * MTP)) * 80;
    const uint32_t bWarpOff = (uint32_t)(warpN * (NTP * 16)) * 80;

    auto load_stage = [&](int c) {
        const uint32_t sb = smem32 + (uint32_t)(c & 1) * (STWd * 4);
        const int kk = kbase + c * 32;
        #pragma unroll
        for (int i = 0; i < UNITS; ++i) {
            const int u = i * 256 + tid;
            if (UNITS * 256 != TOT16 && u >= TOT16) break;
            const __half* src;
            uint32_t dstw;
            if (u < BM * 4) {
                const int row = u >> 2, seg = u & 3;
                src  = A + (size_t)(m0 + row) * lda + kk + seg * 8;
                dstw = row * 20 + seg * 4;
            } else {
                const int v = u - BM * 4;
                const int hsel = v >= BN * 4;
                const int w = v & (BN * 4 - 1);
                const int row = w >> 2, seg = w & 3;
                src  = (hsel ? Bl : Bh) + (size_t)(n0 + row) * ldb + kk + seg * 8;
                dstw = AWd + (hsel ? BWd : 0) + row * 20 + seg * 4;
            }
            CP_ASYNC16(sb + dstw * 4, src);
        }
        CP_COMMIT();
    };

    float acc[MTP][2 * NTP][4];
    #pragma unroll
    for (int i = 0; i < MTP; ++i)
        #pragma unroll
        for (int j = 0; j < 2 * NTP; ++j)
            #pragma unroll
            for (int k = 0; k < 4; ++k) acc[i][j][k] = 0.f;

    load_stage(0);

    for (int c = 0; c < nk; ++c) {
        if (c + 1 < nk) { load_stage(c + 1); CP_WAIT1(); }
        else            { CP_WAIT0(); }
        __syncthreads();

        const uint32_t sb = smem32 + (uint32_t)(c & 1) * (STWd * 4);
        const uint32_t aB = sb + aWarpOff + aLaneOff;
        const uint32_t bB = sb + AWd * 4 + bWarpOff + bLaneOff;

        #pragma unroll
        for (int sub = 0; sub < 2; ++sub) {
            uint32_t af[MTP][4];
            #pragma unroll
            for (int mt = 0; mt < MTP; ++mt)
                ldsm4(af[mt], aB + (uint32_t)mt * (16 * 80) + sub * 32);

            #pragma unroll
            for (int ntp = 0; ntp < NTP; ++ntp) {
                uint32_t bh[4], bl[4];
                ldsm4(bh, bB + (uint32_t)ntp * (16 * 80) + sub * 32);
                ldsm4(bl, bB + BWd * 4 + (uint32_t)ntp * (16 * 80) + sub * 32);
                #pragma unroll
                for (int hf = 0; hf < 2; ++hf) {
                    const int nt = ntp * 2 + hf;
                    #pragma unroll
                    for (int mt = 0; mt < MTP; ++mt) {
                        mma16816(acc[mt][nt], af[mt], bh + hf * 2);
                        mma16816(acc[mt][nt], af[mt], bl + hf * 2);
                    }
                }
            }
        }
        __syncthreads();
    }

    // ---- epilogue ----
    float* out_fz = out_f + (size_t)blockIdx.z * zstride;

    #pragma unroll
    for (int mt = 0; mt < MTP; ++mt) {
        #pragma unroll
        for (int nt = 0; nt < 2 * NTP; ++nt) {
            const int c0 = n0 + warpN * (NTP * 16) + nt * 8 + lanem * 2;
            const int r0 = m0 + warpM * (16 * MTP) + mt * 16 + lane4;

            if (mode == 2) {
                *(float2*)(out_fz + (size_t)r0 * out_ld + c0) =
                    make_float2(acc[mt][nt][0], acc[mt][nt][1]);
                *(float2*)(out_fz + (size_t)(r0 + 8) * out_ld + c0) =
                    make_float2(acc[mt][nt][2], acc[mt][nt][3]);
            } else {
                const float bv0 = bias[c0];
                const float bv1 = bias[c0 + 1];
                *(float2*)(out_fz + (size_t)r0 * out_ld + c0) =
                    make_float2(gelu_exact(acc[mt][nt][0] + bv0),
                                gelu_exact(acc[mt][nt][1] + bv1));
                *(float2*)(out_fz + (size_t)(r0 + 8) * out_ld + c0) =
                    make_float2(gelu_exact(acc[mt][nt][2] + bv0),
                                gelu_exact(acc[mt][nt][3] + bv1));
            }
        }
    }
}

#define GEMM1_SMEM ((2 * (64 * 20 + 2 * 128 * 20)) * 4)   // 51200 B
#define GEMM2_SMEM ((2 * (32 * 20 + 2 *  64 * 20)) * 4)   // 25600 B

// ---------------------------------------------------------------------------
// Combine K-split partials: x1 = gelu(p0 + p1 + b1) -> fp16
// ---------------------------------------------------------------------------
__global__ void combine_kernel(const float* __restrict__ b1)
{
    const int idx = blockIdx.x * blockDim.x + threadIdx.x;   // float4 index
    const float4 p0 = ((const float4*)g_part)[idx];
    const float4 p1 = ((const float4*)g_part)[idx + (BQ * N1) / 4];
    const float4 bv = ((const float4*)b1)[idx & (N1 / 4 - 1)];
    float4 g;
    g.x = gelu_exact(p0.x + p1.x + bv.x);
    g.y = gelu_exact(p0.y + p1.y + bv.y);
    g.z = gelu_exact(p0.z + p1.z + bv.z);
    g.w = gelu_exact(p0.w + p1.w + bv.w);
    store_h4(g_x1, (size_t)idx * 4, g);
}

// ---------------------------------------------------------------------------
// Head: one warp per 8 rows, shuffle reduction over K=128
// ---------------------------------------------------------------------------
__global__ void head_kernel(const float* __restrict__ X,
                            const float* __restrict__ W3,
                            const float* __restrict__ b3,
                            const float* __restrict__ mask,
                            float* __restrict__ out)
{
    const int gwarp = (blockIdx.x * blockDim.x + threadIdx.x) >> 5;
    const int lane  = threadIdx.x & 31;

    const float4 w0 = ((const float4*)W3)[lane];
    const float4 w1 = ((const float4*)W3)[32 + lane];
    const float b30 = b3[0], b31 = b3[1];

    const int rowbase = gwarp * 8;
    #pragma unroll
    for (int i = 0; i < 8; ++i) {
        const int row = rowbase + i;
        const float4 xv = ((const float4*)(X + (size_t)row * N2))[lane];
        float s0 = xv.x * w0.x + xv.y * w0.y + xv.z * w0.z + xv.w * w0.w;
        float s1 = xv.x * w1.x + xv.y * w1.y + xv.z * w1.z + xv.w * w1.w;
        #pragma unroll
        for (int off = 16; off > 0; off >>= 1) {
            s0 += __shfl_xor_sync(0xFFFFFFFFu, s0, off);
            s1 += __shfl_xor_sync(0xFFFFFFFFu, s1, off);
        }
        if (lane == 0) {
            const float mk = (mask[row] >= 0.5f) ? 1.0f : 0.0f;
            const float v0 = (1.0f / (1.0f + expf(-(s0 + b30)))) * 8.0f + 1.0f;
            const float v1 = (1.0f / (1.0f + expf(-(s1 + b31)))) * 8.0f + 1.0f;
            out[row * 2 + 0] = v0 * mk;
            out[row * 2 + 1] = v1 * mk;
        }
    }
}

// ---------------------------------------------------------------------------
// Launch
// ---------------------------------------------------------------------------
extern "C" void kernel_launch(void* const* d_in, const int* in_sizes, int n_in,
                              void* d_out, int out_size)
{
    const float* hidden = (const float*)d_in[0];
    const int*   spans  = (const int*)d_in[1];
    const float* mask   = (const float*)d_in[2];
    const float* W1     = (const float*)d_in[3];
    const float* b1     = (const float*)d_in[4];
    const float* W2     = (const float*)d_in[5];
    const float* b2     = (const float*)d_in[6];
    const float* W3     = (const float*)d_in[7];
    const float* b3     = (const float*)d_in[8];
    float*       out    = (float*)d_out;

    __half *A, *W1h, *W1l, *W2h, *W2l, *x1;
    float  *part, *x2;
    cudaGetSymbolAddress((void**)&A,    g_A);
    cudaGetSymbolAddress((void**)&W1h,  g_W1h);
    cudaGetSymbolAddress((void**)&W1l,  g_W1l);
    cudaGetSymbolAddress((void**)&W2h,  g_W2h);
    cudaGetSymbolAddress((void**)&W2l,  g_W2l);
    cudaGetSymbolAddress((void**)&x1,   g_x1);
    cudaGetSymbolAddress((void**)&part, g_part);
    cudaGetSymbolAddress((void**)&x2,   g_x2);

    cudaFuncSetAttribute((const void*)mma_gemm_kernel<2, 2>,
                         cudaFuncAttributeMaxDynamicSharedMemorySize, GEMM1_SMEM);
    cudaFuncSetAttribute((const void*)mma_gemm_kernel<1, 1>,
                         cudaFuncAttributeMaxDynamicSharedMemorySize, GEMM2_SMEM);

    // 0) weight prep
    prep_w_kernel<<<(N1 * K1 + 255) / 256, 256>>>(W1, W2);

    // 1) pooling + pair features (fp16)
    pool_pair_kernel<<<BQ, 256>>>(hidden, spans);

    // 2) layer 1, K-split partials: grid (2, 64, 2) = 256 CTAs
    {
        dim3 grid(N1 / 128, BQ / 64, 2);
        mma_gemm_kernel<2, 2><<<grid, 256, GEMM1_SMEM>>>(
            A, W1h, W1l, K1, K1, K1 / 2, nullptr,
            part, N1, 2, (size_t)BQ * N1);
    }

    // 3) combine partials: bias + gelu -> fp16 x1
    combine_kernel<<<(BQ * N1 / 4) / 256, 256>>>(b1);

    // 4) layer 2: grid (2, 128) = 256 CTAs, fused bias+gelu, fp32 out
    {
        dim3 grid(N2 / 64, BQ / 32, 1);
        mma_gemm_kernel<1, 1><<<grid, 256, GEMM2_SMEM>>>(
            x1, W2h, W2l, N1, N1, N1, b2,
            x2, N2, 0, 0);
    }

    // 5) head
    head_kernel<<<64, 256>>>(x2, W3, b3, mask, out);
}

// round 9
// speedup vs baseline: 3.4412x; 1.1095x over previous
#include <cuda_runtime.h>
#include <cuda_fp16.h>
#include <math.h>
#include <stdint.h>

// Problem constants
#define BB   32
#define LL   512
#define HH   1024
#define QQ   128
#define BQ   (BB * QQ)        // 4096 pair rows
#define K1   (3 * HH)          // 3072
#define N1   256               // VA_H
#define N2   128               // VA_H/2

// Scratch (static device globals)
__device__ __half g_A[(size_t)BQ * K1];     // pooled pair features, fp16
__device__ __half g_W1[(size_t)N1 * K1];    // fp16 weights
__device__ __half g_W2[(size_t)N2 * N1];
__device__ __half g_x1[(size_t)BQ * N1];    // gelu(layer1), fp16
__device__ float  g_x2[(size_t)BQ * N2];

// ---------------------------------------------------------------------------
// helpers
// ---------------------------------------------------------------------------
__device__ __forceinline__ uint32_t smem_u32(const void* p) {
    uint32_t a;
    asm("{ .reg .u64 t; cvta.to.shared.u64 t, %1; cvt.u32.u64 %0, t; }"
        : "=r"(a) : "l"(p));
    return a;
}

#define CP_ASYNC16(dst, src) \
    asm volatile("cp.async.cg.shared.global [%0], [%1], 16;" :: "r"(dst), "l"(src) : "memory")
#define CP_COMMIT() asm volatile("cp.async.commit_group;" ::: "memory")
#define CP_WAIT0()  asm volatile("cp.async.wait_group 0;" ::: "memory")
#define CP_WAIT1()  asm volatile("cp.async.wait_group 1;" ::: "memory")

__device__ __forceinline__ void mma16816(float c[4],
                                         const uint32_t a[4],
                                         const uint32_t b[2])
{
    asm volatile(
        "mma.sync.aligned.m16n8k16.row.col.f32.f16.f16.f32 "
        "{%0,%1,%2,%3}, {%4,%5,%6,%7}, {%8,%9}, {%0,%1,%2,%3};\n"
        : "+f"(c[0]), "+f"(c[1]), "+f"(c[2]), "+f"(c[3])
        : "r"(a[0]), "r"(a[1]), "r"(a[2]), "r"(a[3]),
          "r"(b[0]), "r"(b[1]));
}

__device__ __forceinline__ void ldsm4(uint32_t r[4], uint32_t addr)
{
    asm volatile("ldmatrix.sync.aligned.m8n8.x4.shared.b16 {%0,%1,%2,%3}, [%4];"
        : "=r"(r[0]), "=r"(r[1]), "=r"(r[2]), "=r"(r[3]) : "r"(addr));
}

__device__ __forceinline__ float gelu_exact(float x) {
    return 0.5f * x * (1.0f + erff(x * 0.70710678118654752f));
}

__device__ __forceinline__ void store_h4(__half* dst, size_t idx, float4 v)
{
    __half2 hh[2] = {
        __halves2half2(__float2half_rn(v.x), __float2half_rn(v.y)),
        __halves2half2(__float2half_rn(v.z), __float2half_rn(v.w)) };
    *(uint2*)(dst + idx) = *(uint2*)hh;
}

// ---------------------------------------------------------------------------
// Weight prep: convert W1, W2 to fp16
// ---------------------------------------------------------------------------
__global__ void prep_w_kernel(const float* __restrict__ W1,
                              const float* __restrict__ W2)
{
    const int i = blockIdx.x * blockDim.x + threadIdx.x;
    if (i < N1 * K1) g_W1[i] = __float2half_rn(W1[i]);
    if (i < N2 * N1) g_W2[i] = __float2half_rn(W2[i]);
}

// ---------------------------------------------------------------------------
// Span pooling + pair features -> fp16
// ---------------------------------------------------------------------------
__global__ void pool_pair_kernel(const float* __restrict__ hs,
                                 const int* __restrict__ spans)
{
    const int bq  = blockIdx.x;
    const int b   = bq >> 7;
    const int tid = threadIdx.x;

    const int* sp = spans + (size_t)bq * 4;
    const int as = sp[0], ae = sp[1], os = sp[2], oe = sp[3];
    const bool av = (as >= 2) && (ae >= as);
    const bool ov = (os >= 2) && (oe >= os);

    const float* base = hs + (size_t)b * LL * HH + 4 * tid;

    float4 aacc = {0.f, 0.f, 0.f, 0.f};
    float4 oacc = {0.f, 0.f, 0.f, 0.f};

    {
        int s = av ? as : 1, e = av ? ae : 1;
        s = min(max(s, 0), LL - 1);
        e = min(max(e, 0), LL - 1);
        const float inv = 1.0f / (float)((e - s + 1) > 0 ? (e - s + 1) : 1);
        for (int r = s; r <= e; ++r) {
            const float4 v = *(const float4*)(base + (size_t)r * HH);
            aacc.x += v.x; aacc.y += v.y; aacc.z += v.z; aacc.w += v.w;
        }
        aacc.x *= inv; aacc.y *= inv; aacc.z *= inv; aacc.w *= inv;
    }
    {
        int s = ov ? os : 1, e = ov ? oe : 1;
        s = min(max(s, 0), LL - 1);
        e = min(max(e, 0), LL - 1);
        const float inv = 1.0f / (float)((e - s + 1) > 0 ? (e - s + 1) : 1);
        for (int r = s; r <= e; ++r) {
            const float4 v = *(const float4*)(base + (size_t)r * HH);
            oacc.x += v.x; oacc.y += v.y; oacc.z += v.z; oacc.w += v.w;
        }
        oacc.x *= inv; oacc.y *= inv; oacc.z *= inv; oacc.w *= inv;
    }

    float4 pacc;
    pacc.x = aacc.x * oacc.x;  pacc.y = aacc.y * oacc.y;
    pacc.z = aacc.z * oacc.z;  pacc.w = aacc.w * oacc.w;

    const size_t rowoff = (size_t)bq * K1 + 4 * tid;
    store_h4(g_A, rowoff,          aacc);
    store_h4(g_A, rowoff + HH,     oacc);
    store_h4(g_A, rowoff + 2 * HH, pacc);
}

// ---------------------------------------------------------------------------
// Pipelined pure-fp16 mma.sync GEMM, fp32 accum, ldmatrix fragments.
// BM=32*MTP, BN=64*NTP, BK=32, 256 threads = 8 warps (2M x 4N).
// 2-stage cp.async double buffering.
// mode 0: out_f = gelu(acc+bias)  fp32
// mode 1: out_h = gelu(acc+bias)  fp16
// ---------------------------------------------------------------------------
template<int MTP, int NTP>
__global__ __launch_bounds__(256)
void mma_gemm_kernel(const __half* __restrict__ A,
                     const __half* __restrict__ B,
                     int lda, int ldb, int K,
                     const float* __restrict__ bias,
                     float* __restrict__ out_f,
                     __half* __restrict__ out_h,
                     int out_ld, int mode)
{
    constexpr int BM    = 32 * MTP;
    constexpr int BN    = 64 * NTP;
    constexpr int AWd   = BM * 20;          // words per A buffer
    constexpr int BWd   = BN * 20;          // words per B buffer
    constexpr int STWd  = AWd + BWd;
    constexpr int TOT16 = (BM + BN) * 4;    // 16B units per stage
    constexpr int UNITS = (TOT16 + 255) / 256;

    extern __shared__ uint32_t sm[];
    const uint32_t smem32 = smem_u32(sm);

    const int tid   = threadIdx.x;
    const int warp  = tid >> 5;
    const int lane  = tid & 31;
    const int warpM = warp >> 2;
    const int warpN = warp & 3;
    const int lane4 = lane >> 2;
    const int lanem = lane & 3;

    const int m0 = blockIdx.y * BM;
    const int n0 = blockIdx.x * BN;
    const int nk = K >> 5;

    const uint32_t aLaneOff = ((lane & 15) * 20 + ((lane >> 4) << 2)) * 4;
    const uint32_t bLaneOff = (((lane & 7) + ((lane >> 4) << 3)) * 20
                               + (((lane >> 3) & 1) << 2)) * 4;
    const uint32_t aWarpOff = (uint32_t)(warpM * (16 * MTP)) * 80;
    const uint32_t bWarpOff = (uint32_t)(warpN * (NTP * 16)) * 80;

    auto load_stage = [&](int c) {
        const uint32_t sb = smem32 + (uint32_t)(c & 1) * (STWd * 4);
        const int kk = c * 32;
        #pragma unroll
        for (int i = 0; i < UNITS; ++i) {
            const int u = i * 256 + tid;
            if (UNITS * 256 != TOT16 && u >= TOT16) break;
            const __half* src;
            uint32_t dstw;
            if (u < BM * 4) {
                const int row = u >> 2, seg = u & 3;
                src  = A + (size_t)(m0 + row) * lda + kk + seg * 8;
                dstw = row * 20 + seg * 4;
            } else {
                const int v = u - BM * 4;
                const int row = v >> 2, seg = v & 3;
                src  = B + (size_t)(n0 + row) * ldb + kk + seg * 8;
                dstw = AWd + row * 20 + seg * 4;
            }
            CP_ASYNC16(sb + dstw * 4, src);
        }
        CP_COMMIT();
    };

    float acc[MTP][2 * NTP][4];
    #pragma unroll
    for (int i = 0; i < MTP; ++i)
        #pragma unroll
        for (int j = 0; j < 2 * NTP; ++j)
            #pragma unroll
            for (int k = 0; k < 4; ++k) acc[i][j][k] = 0.f;

    load_stage(0);

    for (int c = 0; c < nk; ++c) {
        if (c + 1 < nk) { load_stage(c + 1); CP_WAIT1(); }
        else            { CP_WAIT0(); }
        __syncthreads();

        const uint32_t sb = smem32 + (uint32_t)(c & 1) * (STWd * 4);
        const uint32_t aB = sb + aWarpOff + aLaneOff;
        const uint32_t bB = sb + AWd * 4 + bWarpOff + bLaneOff;

        #pragma unroll
        for (int sub = 0; sub < 2; ++sub) {
            uint32_t af[MTP][4];
            #pragma unroll
            for (int mt = 0; mt < MTP; ++mt)
                ldsm4(af[mt], aB + (uint32_t)mt * (16 * 80) + sub * 32);

            #pragma unroll
            for (int ntp = 0; ntp < NTP; ++ntp) {
                uint32_t bf[4];
                ldsm4(bf, bB + (uint32_t)ntp * (16 * 80) + sub * 32);
                #pragma unroll
                for (int hf = 0; hf < 2; ++hf) {
                    const int nt = ntp * 2 + hf;
                    #pragma unroll
                    for (int mt = 0; mt < MTP; ++mt)
                        mma16816(acc[mt][nt], af[mt], bf + hf * 2);
                }
            }
        }
        __syncthreads();
    }

    // ---- epilogue: bias + gelu ----
    #pragma unroll
    for (int mt = 0; mt < MTP; ++mt) {
        #pragma unroll
        for (int nt = 0; nt < 2 * NTP; ++nt) {
            const int c0 = n0 + warpN * (NTP * 16) + nt * 8 + lanem * 2;
            const int r0 = m0 + warpM * (16 * MTP) + mt * 16 + lane4;
            const float bv0 = bias[c0];
            const float bv1 = bias[c0 + 1];

            const float g00 = gelu_exact(acc[mt][nt][0] + bv0);
            const float g01 = gelu_exact(acc[mt][nt][1] + bv1);
            const float g10 = gelu_exact(acc[mt][nt][2] + bv0);
            const float g11 = gelu_exact(acc[mt][nt][3] + bv1);

            if (mode == 0) {
                *(float2*)(out_f + (size_t)r0 * out_ld + c0)       = make_float2(g00, g01);
                *(float2*)(out_f + (size_t)(r0 + 8) * out_ld + c0) = make_float2(g10, g11);
            } else {
                *(__half2*)(out_h + (size_t)r0 * out_ld + c0) =
                    __halves2half2(__float2half_rn(g00), __float2half_rn(g01));
                *(__half2*)(out_h + (size_t)(r0 + 8) * out_ld + c0) =
                    __halves2half2(__float2half_rn(g10), __float2half_rn(g11));
            }
        }
    }
}

#define GEMM1_SMEM ((2 * (32 * 20 + 128 * 20)) * 4)   // 25600 B
#define GEMM2_SMEM ((2 * (32 * 20 +  64 * 20)) * 4)   // 15360 B

// ---------------------------------------------------------------------------
// Head: one warp per 8 rows, shuffle reduction over K=128
// ---------------------------------------------------------------------------
__global__ void head_kernel(const float* __restrict__ X,
                            const float* __restrict__ W3,
                            const float* __restrict__ b3,
                            const float* __restrict__ mask,
                            float* __restrict__ out)
{
    const int gwarp = (blockIdx.x * blockDim.x + threadIdx.x) >> 5;
    const int lane  = threadIdx.x & 31;

    const float4 w0 = ((const float4*)W3)[lane];
    const float4 w1 = ((const float4*)W3)[32 + lane];
    const float b30 = b3[0], b31 = b3[1];

    const int rowbase = gwarp * 8;
    #pragma unroll
    for (int i = 0; i < 8; ++i) {
        const int row = rowbase + i;
        const float4 xv = ((const float4*)(X + (size_t)row * N2))[lane];
        float s0 = xv.x * w0.x + xv.y * w0.y + xv.z * w0.z + xv.w * w0.w;
        float s1 = xv.x * w1.x + xv.y * w1.y + xv.z * w1.z + xv.w * w1.w;
        #pragma unroll
        for (int off = 16; off > 0; off >>= 1) {
            s0 += __shfl_xor_sync(0xFFFFFFFFu, s0, off);
            s1 += __shfl_xor_sync(0xFFFFFFFFu, s1, off);
        }
        if (lane == 0) {
            const float mk = (mask[row] >= 0.5f) ? 1.0f : 0.0f;
            const float v0 = (1.0f / (1.0f + expf(-(s0 + b30)))) * 8.0f + 1.0f;
            const float v1 = (1.0f / (1.0f + expf(-(s1 + b31)))) * 8.0f + 1.0f;
            out[row * 2 + 0] = v0 * mk;
            out[row * 2 + 1] = v1 * mk;
        }
    }
}

// ---------------------------------------------------------------------------
// Launch
// ---------------------------------------------------------------------------
extern "C" void kernel_launch(void* const* d_in, const int* in_sizes, int n_in,
                              void* d_out, int out_size)
{
    const float* hidden = (const float*)d_in[0];
    const int*   spans  = (const int*)d_in[1];
    const float* mask   = (const float*)d_in[2];
    const float* W1     = (const float*)d_in[3];
    const float* b1     = (const float*)d_in[4];
    const float* W2     = (const float*)d_in[5];
    const float* b2     = (const float*)d_in[6];
    const float* W3     = (const float*)d_in[7];
    const float* b3     = (const float*)d_in[8];
    float*       out    = (float*)d_out;

    __half *A, *W1h, *W2h, *x1;
    float  *x2;
    cudaGetSymbolAddress((void**)&A,   g_A);
    cudaGetSymbolAddress((void**)&W1h, g_W1);
    cudaGetSymbolAddress((void**)&W2h, g_W2);
    cudaGetSymbolAddress((void**)&x1,  g_x1);
    cudaGetSymbolAddress((void**)&x2,  g_x2);

    cudaFuncSetAttribute((const void*)mma_gemm_kernel<1, 2>,
                         cudaFuncAttributeMaxDynamicSharedMemorySize, GEMM1_SMEM);
    cudaFuncSetAttribute((const void*)mma_gemm_kernel<1, 1>,
                         cudaFuncAttributeMaxDynamicSharedMemorySize, GEMM2_SMEM);

    // 0) weight prep (fp32 -> fp16)
    prep_w_kernel<<<(N1 * K1 + 255) / 256, 256>>>(W1, W2);

    // 1) pooling + pair features (fp16)
    pool_pair_kernel<<<BQ, 256>>>(hidden, spans);

    // 2) layer 1: grid (2, 128) = 256 CTAs, fused bias+gelu -> fp16 x1
    {
        dim3 grid(N1 / 128, BQ / 32);
        mma_gemm_kernel<1, 2><<<grid, 256, GEMM1_SMEM>>>(
            A, W1h, K1, K1, K1, b1, nullptr, x1, N1, 1);
    }

    // 3) layer 2: grid (2, 128) = 256 CTAs, fused bias+gelu -> fp32 x2
    {
        dim3 grid(N2 / 64, BQ / 32);
        mma_gemm_kernel<1, 1><<<grid, 256, GEMM2_SMEM>>>(
            x1, W2h, N1, N1, N1, b2, x2, nullptr, N2, 0);
    }

    // 4) head
    head_kernel<<<64, 256>>>(x2, W3, b3, mask, out);
}